// round 10
// baseline (speedup 1.0000x reference)
#include <cuda_runtime.h>
#include <math.h>

#define NN 100000
#define EE 1600000
#define F_IN 512
#define FF1 64
#define DD2 40

// ---------------- scratch ----------------
__device__ float g_hs1[NN * FF1];
__device__ float g_hd1[NN * FF1];
__device__ float g_s1[NN * 8];
__device__ float g_h1[NN * FF1];
__device__ float g_hs2[NN * DD2];
__device__ float g_hd2[NN * DD2];
__device__ float g_s2[NN];

// ---------------- PTX helpers ----------------
__device__ __forceinline__ unsigned f2tf32(float f) {
    unsigned u;
    asm("cvt.rna.tf32.f32 %0, %1;" : "=r"(u) : "f"(f));
    return u;
}
__device__ __forceinline__ void redv4(float* addr, float a, float b, float c, float d) {
    asm volatile("red.global.add.v4.f32 [%0], {%1,%2,%3,%4};"
                 :: "l"(addr), "f"(a), "f"(b), "f"(c), "f"(d) : "memory");
}
__device__ __forceinline__ void red1(float* addr, float a) {
    asm volatile("red.global.add.f32 [%0], %1;" :: "l"(addr), "f"(a) : "memory");
}
__device__ __forceinline__ void mma_tf32(float* acc, const unsigned* a, const unsigned* b) {
    asm volatile(
        "mma.sync.aligned.m16n8k8.row.col.f32.tf32.tf32.f32 "
        "{%0,%1,%2,%3}, {%4,%5,%6,%7}, {%8,%9}, {%0,%1,%2,%3};"
        : "+f"(acc[0]), "+f"(acc[1]), "+f"(acc[2]), "+f"(acc[3])
        : "r"(a[0]), "r"(a[1]), "r"(a[2]), "r"(a[3]), "r"(b[0]), "r"(b[1]));
}
__device__ __forceinline__ void cp_async16(void* smem_dst, const void* gsrc) {
    unsigned saddr = (unsigned)__cvta_generic_to_shared(smem_dst);
    asm volatile("cp.async.cg.shared.global [%0], [%1], 16;" :: "r"(saddr), "l"(gsrc));
}
__device__ __forceinline__ void cp_commit() { asm volatile("cp.async.commit_group;"); }
__device__ __forceinline__ void cp_wait0() { asm volatile("cp.async.wait_group 0;"); }
__device__ __forceinline__ void cp_wait1() { asm volatile("cp.async.wait_group 1;"); }

// ---------------- zero kernels ----------------
__global__ void k_zero2(float* a, int na, float* b, int nb) {
    int i = blockIdx.x * blockDim.x + threadIdx.x;
    if (i < na) a[i] = 0.f;
    if (i < nb) b[i] = 0.f;
}

// ================= layer-1 GEMM: tf32 mma, 3-stage cp.async =================
#define BM 64
#define BK 16
#define APAD2 20
#define BPAD2 136
#define NSTAGE 3
__global__ __launch_bounds__(256, 3)
void k_gemm1_mma(const float* __restrict__ A,
                 const float* __restrict__ W1, const float* __restrict__ b1,
                 const float* __restrict__ W2, const float* __restrict__ b2,
                 float* __restrict__ C1, float* __restrict__ C2) {
    __shared__ float As[NSTAGE][BM * APAD2];
    __shared__ float Bs[NSTAGE][BK * BPAD2];

    const int tid = threadIdx.x;
    const int lane = tid & 31, warp = tid >> 5;
    const int wr = warp & 1, wc = warp >> 1;
    const int g = lane >> 2, tg = lane & 3;
    const int row0 = blockIdx.x * BM;

    float acc[2][4][4];
#pragma unroll
    for (int mi = 0; mi < 2; mi++)
#pragma unroll
        for (int ni = 0; ni < 4; ni++)
#pragma unroll
            for (int r = 0; r < 4; r++) acc[mi][ni][r] = 0.f;

    const int rA = tid >> 2, qA = tid & 3;
    const int rAg = min(row0 + rA, NN - 1);
    const float* gA = A + (size_t)rAg * F_IN + qA * 4;
    const int sAoff = rA * APAD2 + qA * 4;

    const int kB = tid >> 5;
    const int cB = (tid & 31) * 4;
    const float* gBsrc = (cB < 64) ? (W1 + kB * 64 + cB) : (W2 + kB * 64 + cB - 64);
    const int sBoff0 = kB * BPAD2 + cB;
    const int sBoff1 = (kB + 8) * BPAD2 + cB;

    auto issue = [&](int it) {
        const int buf = it % NSTAGE;
        const int kc = it * BK;
        cp_async16(&As[buf][sAoff], gA + kc);
        cp_async16(&Bs[buf][sBoff0], gBsrc + kc * 64);
        cp_async16(&Bs[buf][sBoff1], gBsrc + (kc + 8) * 64);
        cp_commit();
    };

    const int NITER = F_IN / BK;   // 32
    issue(0);
    issue(1);
    for (int it = 0; it < NITER; it++) {
        cp_wait1();
        __syncthreads();
        if (it + 2 < NITER) issue(it + 2);
        else cp_commit();
        const int buf = it % NSTAGE;

#pragma unroll
        for (int ks = 0; ks < 2; ks++) {
            const int k0 = ks * 8;
            unsigned afr[2][4], bfr[4][2];
#pragma unroll
            for (int mi = 0; mi < 2; mi++) {
                const int base = wr * 32 + mi * 16;
                afr[mi][0] = f2tf32(As[buf][(base + g) * APAD2 + k0 + tg]);
                afr[mi][1] = f2tf32(As[buf][(base + g + 8) * APAD2 + k0 + tg]);
                afr[mi][2] = f2tf32(As[buf][(base + g) * APAD2 + k0 + tg + 4]);
                afr[mi][3] = f2tf32(As[buf][(base + g + 8) * APAD2 + k0 + tg + 4]);
            }
#pragma unroll
            for (int ni = 0; ni < 4; ni++) {
                const int col = wc * 32 + ni * 8 + g;
                bfr[ni][0] = f2tf32(Bs[buf][(k0 + tg) * BPAD2 + col]);
                bfr[ni][1] = f2tf32(Bs[buf][(k0 + tg + 4) * BPAD2 + col]);
            }
#pragma unroll
            for (int mi = 0; mi < 2; mi++)
#pragma unroll
                for (int ni = 0; ni < 4; ni++)
                    mma_tf32(acc[mi][ni], afr[mi], bfr[ni]);
        }
    }

    float* Cw = (wc < 2) ? C1 : C2;
    const float* bw = (wc < 2) ? b1 : b2;
    const int cbase = (wc < 2) ? wc * 32 : (wc - 2) * 32;
#pragma unroll
    for (int mi = 0; mi < 2; mi++) {
#pragma unroll
        for (int ni = 0; ni < 4; ni++) {
            const int col = cbase + ni * 8 + 2 * tg;
            const float bb0 = __ldg(bw + col), bb1 = __ldg(bw + col + 1);
            const int r0 = row0 + wr * 32 + mi * 16 + g;
            const int r1 = r0 + 8;
            if (r0 < NN) {
                float2 v = make_float2(acc[mi][ni][0] + bb0, acc[mi][ni][1] + bb1);
                *reinterpret_cast<float2*>(Cw + (size_t)r0 * 64 + col) = v;
            }
            if (r1 < NN) {
                float2 v = make_float2(acc[mi][ni][2] + bb0, acc[mi][ni][3] + bb1);
                *reinterpret_cast<float2*>(Cw + (size_t)r1 * 64 + col) = v;
            }
        }
    }
}

// ================= layer-2 GEMM: tf32 mma (K=64, M=40 dual) =================
#define BM2 128
#define APAD3 20
#define BPW 88
__global__ __launch_bounds__(256, 2)
void k_gemm2_mma(const float* __restrict__ A,
                 const float* __restrict__ W1, const float* __restrict__ b1,
                 const float* __restrict__ W2, const float* __restrict__ b2,
                 float* __restrict__ C1, float* __restrict__ C2) {
    __shared__ float As[2][BM2 * APAD3];
    __shared__ float Bs[2][BK * BPW];

    const int tid = threadIdx.x;
    const int lane = tid & 31, warp = tid >> 5;
    const int wr = warp & 3, wc = warp >> 2;
    const int g = lane >> 2, tg = lane & 3;
    const int row0 = blockIdx.x * BM2;

    float acc[2][5][4];
#pragma unroll
    for (int mi = 0; mi < 2; mi++)
#pragma unroll
        for (int ni = 0; ni < 5; ni++)
#pragma unroll
            for (int r = 0; r < 4; r++) acc[mi][ni][r] = 0.f;

    const int rA = tid >> 2, qA = tid & 3;
    const int rAg0 = min(row0 + rA, NN - 1);
    const int rAg1 = min(row0 + rA + 64, NN - 1);
    const float* gA0 = A + (size_t)rAg0 * FF1 + qA * 4;
    const float* gA1 = A + (size_t)rAg1 * FF1 + qA * 4;
    const int sAoff0 = rA * APAD3 + qA * 4;
    const int sAoff1 = (rA + 64) * APAD3 + qA * 4;

    const int i0 = tid;
    const int kB0 = i0 / 20, c40 = i0 % 20;
    const int i1 = 256 + tid;
    const int kB1 = i1 / 20, c41 = i1 % 20;
    const int cB0 = c40 * 4, cB1 = c41 * 4;
    const float* gB0 = (cB0 < 40) ? (W1 + kB0 * 40 + cB0) : (W2 + kB0 * 40 + cB0 - 40);
    const float* gB1 = (cB1 < 40) ? (W1 + kB1 * 40 + cB1) : (W2 + kB1 * 40 + cB1 - 40);
    const int sB0 = kB0 * BPW + cB0;
    const int sB1 = kB1 * BPW + cB1;

    auto issue = [&](int it) {
        const int buf = it & 1;
        const int kc = it * BK;
        cp_async16(&As[buf][sAoff0], gA0 + kc);
        cp_async16(&As[buf][sAoff1], gA1 + kc);
        cp_async16(&Bs[buf][sB0], gB0 + kc * 40);
        if (tid < 64) cp_async16(&Bs[buf][sB1], gB1 + kc * 40);
        cp_commit();
    };

    const int NITER = FF1 / BK;   // 4
    issue(0);
    for (int it = 0; it < NITER; it++) {
        cp_wait0();
        __syncthreads();
        if (it + 1 < NITER) issue(it + 1);
        const int buf = it & 1;

#pragma unroll
        for (int ks = 0; ks < 2; ks++) {
            const int k0 = ks * 8;
            unsigned afr[2][4], bfr[5][2];
#pragma unroll
            for (int mi = 0; mi < 2; mi++) {
                const int base = wr * 32 + mi * 16;
                afr[mi][0] = f2tf32(As[buf][(base + g) * APAD3 + k0 + tg]);
                afr[mi][1] = f2tf32(As[buf][(base + g + 8) * APAD3 + k0 + tg]);
                afr[mi][2] = f2tf32(As[buf][(base + g) * APAD3 + k0 + tg + 4]);
                afr[mi][3] = f2tf32(As[buf][(base + g + 8) * APAD3 + k0 + tg + 4]);
            }
#pragma unroll
            for (int ni = 0; ni < 5; ni++) {
                const int col = wc * 40 + ni * 8 + g;
                bfr[ni][0] = f2tf32(Bs[buf][(k0 + tg) * BPW + col]);
                bfr[ni][1] = f2tf32(Bs[buf][(k0 + tg + 4) * BPW + col]);
            }
#pragma unroll
            for (int mi = 0; mi < 2; mi++)
#pragma unroll
                for (int ni = 0; ni < 5; ni++)
                    mma_tf32(acc[mi][ni], afr[mi], bfr[ni]);
        }
    }

    float* Cw = (wc == 0) ? C1 : C2;
    const float* bw = (wc == 0) ? b1 : b2;
#pragma unroll
    for (int mi = 0; mi < 2; mi++) {
#pragma unroll
        for (int ni = 0; ni < 5; ni++) {
            const int col = ni * 8 + 2 * tg;
            const float bb0 = __ldg(bw + col), bb1 = __ldg(bw + col + 1);
            const int r0 = row0 + wr * 32 + mi * 16 + g;
            const int r1 = r0 + 8;
            if (r0 < NN) {
                float2 v = make_float2(acc[mi][ni][0] + bb0, acc[mi][ni][1] + bb1);
                *reinterpret_cast<float2*>(Cw + (size_t)r0 * 40 + col) = v;
            }
            if (r1 < NN) {
                float2 v = make_float2(acc[mi][ni][2] + bb0, acc[mi][ni][3] + bb1);
                *reinterpret_cast<float2*>(Cw + (size_t)r1 * 40 + col) = v;
            }
        }
    }
}

// ========== fused layer-1 edge pass: 16 threads/edge, one float4 each ==========
__global__ __launch_bounds__(256)
void k_edge_agg1(const float* __restrict__ hs, const float* __restrict__ hd,
                 const float* __restrict__ attn,
                 const int* __restrict__ src, const int* __restrict__ dst,
                 float* __restrict__ s, float* __restrict__ acc) {
    int idx = blockIdx.x * blockDim.x + threadIdx.x;   // EE*16 exact
    int e = idx >> 4, j = idx & 15;                    // j: feature quad 0..15
    int lane = threadIdx.x & 31;
    int sn = __ldg(src + e), tn = __ldg(dst + e);

    float4 a = *reinterpret_cast<const float4*>(hs + (size_t)sn * 64 + j * 4);
    float4 b = *reinterpret_cast<const float4*>(hd + (size_t)tn * 64 + j * 4);
    float4 w = __ldg(reinterpret_cast<const float4*>(attn + j * 4));

    // partial logit for head j>>1 (this thread covers 4 of its 8 dims)
    float part, x;
    x = a.x + b.x; part = (x > 0.f ? x : 0.2f * x) * w.x;
    x = a.y + b.y; part = fmaf((x > 0.f ? x : 0.2f * x), w.y, part);
    x = a.z + b.z; part = fmaf((x > 0.f ? x : 0.2f * x), w.z, part);
    x = a.w + b.w; part = fmaf((x > 0.f ? x : 0.2f * x), w.w, part);
    part += __shfl_xor_sync(0xffffffffu, part, 1);     // pair j, j^1 = same head
    float p = __expf(part);

    // accumulator RED: one v4 per thread covers the full 64-f row per edge
    redv4(acc + (size_t)tn * 64 + j * 4, p * a.x, p * a.y, p * a.z, p * a.w);

    // s RED: lanes with (j&7)==0 gather p of heads {j/2 .. j/2+3} (lanes +0,+2,+4,+6)
    int base = lane & ~7;
    float v0 = __shfl_sync(0xffffffffu, p, base);
    float v1 = __shfl_sync(0xffffffffu, p, base + 2);
    float v2 = __shfl_sync(0xffffffffu, p, base + 4);
    float v3 = __shfl_sync(0xffffffffu, p, base + 6);
    if ((j & 7) == 0)
        redv4(s + (size_t)tn * 8 + (j >> 1), v0, v1, v2, v3);
}

// ---- scale1: h1 = elu(acc / (s + eps)) ----
__global__ void k_scale1(float* __restrict__ acc, const float* __restrict__ s) {
    int i = blockIdx.x * blockDim.x + threadIdx.x;
    if (i >= NN * 16) return;
    int t = i >> 4, q = i & 15;
    float inv = 1.f / (__ldg(s + t * 8 + (q >> 1)) + 1e-9f);
    float4 v = *reinterpret_cast<float4*>(acc + (size_t)t * 64 + q * 4);
    v.x *= inv; v.y *= inv; v.z *= inv; v.w *= inv;
    v.x = v.x > 0.f ? v.x : (__expf(v.x) - 1.f);
    v.y = v.y > 0.f ? v.y : (__expf(v.y) - 1.f);
    v.z = v.z > 0.f ? v.z : (__expf(v.z) - 1.f);
    v.w = v.w > 0.f ? v.w : (__expf(v.w) - 1.f);
    *reinterpret_cast<float4*>(acc + (size_t)t * 64 + q * 4) = v;
}

// ========== fused layer-2 edge pass: 16 threads/edge, 10 active ==========
__global__ __launch_bounds__(256)
void k_edge_agg2(const float* __restrict__ hs, const float* __restrict__ hd,
                 const float* __restrict__ attn,
                 const int* __restrict__ src, const int* __restrict__ dst,
                 float* __restrict__ s, float* __restrict__ out) {
    int idx = blockIdx.x * blockDim.x + threadIdx.x;   // EE*16 exact
    int e = idx >> 4, j = idx & 15;
    int sn = __ldg(src + e), tn = __ldg(dst + e);
    bool act = j < 10;

    float4 a = make_float4(0.f, 0.f, 0.f, 0.f), b = a, w = a;
    if (act) {
        a = *reinterpret_cast<const float4*>(hs + (size_t)sn * 40 + j * 4);
        b = *reinterpret_cast<const float4*>(hd + (size_t)tn * 40 + j * 4);
        w = __ldg(reinterpret_cast<const float4*>(attn + j * 4));
    }

    float part, x;
    x = a.x + b.x; part = (x > 0.f ? x : 0.2f * x) * w.x;
    x = a.y + b.y; part = fmaf((x > 0.f ? x : 0.2f * x), w.y, part);
    x = a.z + b.z; part = fmaf((x > 0.f ? x : 0.2f * x), w.z, part);
    x = a.w + b.w; part = fmaf((x > 0.f ? x : 0.2f * x), w.w, part);
    // 16-wide xor reduction (groups are 16-aligned within the warp)
    part += __shfl_xor_sync(0xffffffffu, part, 8);
    part += __shfl_xor_sync(0xffffffffu, part, 4);
    part += __shfl_xor_sync(0xffffffffu, part, 2);
    part += __shfl_xor_sync(0xffffffffu, part, 1);
    float p = __expf(part);

    if (act)
        redv4(out + (size_t)tn * 40 + j * 4, p * a.x, p * a.y, p * a.z, p * a.w);
    if (j == 0)
        red1(s + tn, p);
}

// ---- scale2: out = acc / (s + eps) ----
__global__ void k_scale2(float* __restrict__ out, const float* __restrict__ s) {
    int i = blockIdx.x * blockDim.x + threadIdx.x;
    if (i >= NN * 10) return;
    int t = i / 10, q = i - t * 10;
    float inv = 1.f / (__ldg(s + t) + 1e-9f);
    float4 v = *reinterpret_cast<float4*>(out + (size_t)t * 40 + q * 4);
    v.x *= inv; v.y *= inv; v.z *= inv; v.w *= inv;
    *reinterpret_cast<float4*>(out + (size_t)t * 40 + q * 4) = v;
}

// ================= launch =================
extern "C" void kernel_launch(void* const* d_in, const int* in_sizes, int n_in,
                              void* d_out, int out_size) {
    const float* x   = (const float*)d_in[0];
    const int*   src = (const int*)d_in[1];
    const int*   dst = (const int*)d_in[2];
    const float* W1s = (const float*)d_in[3];
    const float* b1s = (const float*)d_in[4];
    const float* W1d = (const float*)d_in[5];
    const float* b1d = (const float*)d_in[6];
    const float* a1  = (const float*)d_in[7];
    const float* W2s = (const float*)d_in[8];
    const float* b2s = (const float*)d_in[9];
    const float* W2d = (const float*)d_in[10];
    const float* b2d = (const float*)d_in[11];
    const float* a2  = (const float*)d_in[12];
    float* out = (float*)d_out;

    float *hs1, *hd1, *s1, *h1, *hs2, *hd2, *s2;
    cudaGetSymbolAddress((void**)&hs1, g_hs1);
    cudaGetSymbolAddress((void**)&hd1, g_hd1);
    cudaGetSymbolAddress((void**)&s1,  g_s1);
    cudaGetSymbolAddress((void**)&h1,  g_h1);
    cudaGetSymbolAddress((void**)&hs2, g_hs2);
    cudaGetSymbolAddress((void**)&hd2, g_hd2);
    cudaGetSymbolAddress((void**)&s2,  g_s2);

    const int T = 256;

    // #1: zero h1+s1 ; #2: gemm1 ; #3: zero s2+out ; #4: edge_agg1 (profiled)
    k_zero2<<<(NN * FF1 + T - 1) / T, T>>>(h1, NN * FF1, s1, NN * 8);
    k_gemm1_mma<<<(NN + BM - 1) / BM, 256>>>(x, W1s, b1s, W1d, b1d, hs1, hd1);
    k_zero2<<<(NN * DD2 + T - 1) / T, T>>>(out, NN * DD2, s2, NN);
    k_edge_agg1<<<EE * 16 / T, T>>>(hs1, hd1, a1, src, dst, s1, h1);         // #4
    k_scale1<<<(NN * 16 + T - 1) / T, T>>>(h1, s1);

    // ---- layer 2 ----
    k_gemm2_mma<<<(NN + BM2 - 1) / BM2, 256>>>(h1, W2s, b2s, W2d, b2d, hs2, hd2);
    k_edge_agg2<<<EE * 16 / T, T>>>(hs2, hd2, a2, src, dst, s2, out);
    k_scale2<<<(NN * 10 + T - 1) / T, T>>>(out, s2);
}

// round 11
// speedup vs baseline: 1.0245x; 1.0245x over previous
#include <cuda_runtime.h>
#include <math.h>

#define NN 100000
#define EE 1600000
#define F_IN 512
#define FF1 64
#define DD2 40

// ---------------- scratch ----------------
__device__ float g_hs1[NN * FF1];
__device__ float g_hd1[NN * FF1];
__device__ float g_s1[NN * 8];
__device__ float g_h1[NN * FF1];
__device__ float g_hs2[NN * DD2];
__device__ float g_hd2[NN * DD2];
__device__ float g_s2[NN];

// ---------------- PTX helpers ----------------
__device__ __forceinline__ unsigned f2tf32(float f) {
    unsigned u;
    asm("cvt.rna.tf32.f32 %0, %1;" : "=r"(u) : "f"(f));
    return u;
}
__device__ __forceinline__ void redv4(float* addr, float a, float b, float c, float d) {
    asm volatile("red.global.add.v4.f32 [%0], {%1,%2,%3,%4};"
                 :: "l"(addr), "f"(a), "f"(b), "f"(c), "f"(d) : "memory");
}
__device__ __forceinline__ void red1(float* addr, float a) {
    asm volatile("red.global.add.f32 [%0], %1;" :: "l"(addr), "f"(a) : "memory");
}
__device__ __forceinline__ void mma_tf32(float* acc, const unsigned* a, const unsigned* b) {
    asm volatile(
        "mma.sync.aligned.m16n8k8.row.col.f32.tf32.tf32.f32 "
        "{%0,%1,%2,%3}, {%4,%5,%6,%7}, {%8,%9}, {%0,%1,%2,%3};"
        : "+f"(acc[0]), "+f"(acc[1]), "+f"(acc[2]), "+f"(acc[3])
        : "r"(a[0]), "r"(a[1]), "r"(a[2]), "r"(a[3]), "r"(b[0]), "r"(b[1]));
}
__device__ __forceinline__ void cp_async16(void* smem_dst, const void* gsrc) {
    unsigned saddr = (unsigned)__cvta_generic_to_shared(smem_dst);
    asm volatile("cp.async.cg.shared.global [%0], [%1], 16;" :: "r"(saddr), "l"(gsrc));
}
__device__ __forceinline__ void cp_commit() { asm volatile("cp.async.commit_group;"); }
__device__ __forceinline__ void cp_wait0() { asm volatile("cp.async.wait_group 0;"); }
__device__ __forceinline__ void cp_wait1() { asm volatile("cp.async.wait_group 1;"); }

// ---------------- zero kernels ----------------
__global__ void k_zero2(float* a, int na, float* b, int nb) {
    int i = blockIdx.x * blockDim.x + threadIdx.x;
    if (i < na) a[i] = 0.f;
    if (i < nb) b[i] = 0.f;
}

// ================= layer-1 GEMM: tf32 mma, 3-stage cp.async =================
#define BM 64
#define BK 16
#define APAD2 20
#define BPAD2 136
#define NSTAGE 3
__global__ __launch_bounds__(256, 3)
void k_gemm1_mma(const float* __restrict__ A,
                 const float* __restrict__ W1, const float* __restrict__ b1,
                 const float* __restrict__ W2, const float* __restrict__ b2,
                 float* __restrict__ C1, float* __restrict__ C2) {
    __shared__ float As[NSTAGE][BM * APAD2];
    __shared__ float Bs[NSTAGE][BK * BPAD2];

    const int tid = threadIdx.x;
    const int lane = tid & 31, warp = tid >> 5;
    const int wr = warp & 1, wc = warp >> 1;
    const int g = lane >> 2, tg = lane & 3;
    const int row0 = blockIdx.x * BM;

    float acc[2][4][4];
#pragma unroll
    for (int mi = 0; mi < 2; mi++)
#pragma unroll
        for (int ni = 0; ni < 4; ni++)
#pragma unroll
            for (int r = 0; r < 4; r++) acc[mi][ni][r] = 0.f;

    const int rA = tid >> 2, qA = tid & 3;
    const int rAg = min(row0 + rA, NN - 1);
    const float* gA = A + (size_t)rAg * F_IN + qA * 4;
    const int sAoff = rA * APAD2 + qA * 4;

    const int kB = tid >> 5;
    const int cB = (tid & 31) * 4;
    const float* gBsrc = (cB < 64) ? (W1 + kB * 64 + cB) : (W2 + kB * 64 + cB - 64);
    const int sBoff0 = kB * BPAD2 + cB;
    const int sBoff1 = (kB + 8) * BPAD2 + cB;

    auto issue = [&](int it) {
        const int buf = it % NSTAGE;
        const int kc = it * BK;
        cp_async16(&As[buf][sAoff], gA + kc);
        cp_async16(&Bs[buf][sBoff0], gBsrc + kc * 64);
        cp_async16(&Bs[buf][sBoff1], gBsrc + (kc + 8) * 64);
        cp_commit();
    };

    const int NITER = F_IN / BK;   // 32
    issue(0);
    issue(1);
    for (int it = 0; it < NITER; it++) {
        cp_wait1();
        __syncthreads();
        if (it + 2 < NITER) issue(it + 2);
        else cp_commit();
        const int buf = it % NSTAGE;

#pragma unroll
        for (int ks = 0; ks < 2; ks++) {
            const int k0 = ks * 8;
            unsigned afr[2][4], bfr[4][2];
#pragma unroll
            for (int mi = 0; mi < 2; mi++) {
                const int base = wr * 32 + mi * 16;
                afr[mi][0] = f2tf32(As[buf][(base + g) * APAD2 + k0 + tg]);
                afr[mi][1] = f2tf32(As[buf][(base + g + 8) * APAD2 + k0 + tg]);
                afr[mi][2] = f2tf32(As[buf][(base + g) * APAD2 + k0 + tg + 4]);
                afr[mi][3] = f2tf32(As[buf][(base + g + 8) * APAD2 + k0 + tg + 4]);
            }
#pragma unroll
            for (int ni = 0; ni < 4; ni++) {
                const int col = wc * 32 + ni * 8 + g;
                bfr[ni][0] = f2tf32(Bs[buf][(k0 + tg) * BPAD2 + col]);
                bfr[ni][1] = f2tf32(Bs[buf][(k0 + tg + 4) * BPAD2 + col]);
            }
#pragma unroll
            for (int mi = 0; mi < 2; mi++)
#pragma unroll
                for (int ni = 0; ni < 4; ni++)
                    mma_tf32(acc[mi][ni], afr[mi], bfr[ni]);
        }
    }

    float* Cw = (wc < 2) ? C1 : C2;
    const float* bw = (wc < 2) ? b1 : b2;
    const int cbase = (wc < 2) ? wc * 32 : (wc - 2) * 32;
#pragma unroll
    for (int mi = 0; mi < 2; mi++) {
#pragma unroll
        for (int ni = 0; ni < 4; ni++) {
            const int col = cbase + ni * 8 + 2 * tg;
            const float bb0 = __ldg(bw + col), bb1 = __ldg(bw + col + 1);
            const int r0 = row0 + wr * 32 + mi * 16 + g;
            const int r1 = r0 + 8;
            if (r0 < NN) {
                float2 v = make_float2(acc[mi][ni][0] + bb0, acc[mi][ni][1] + bb1);
                *reinterpret_cast<float2*>(Cw + (size_t)r0 * 64 + col) = v;
            }
            if (r1 < NN) {
                float2 v = make_float2(acc[mi][ni][2] + bb0, acc[mi][ni][3] + bb1);
                *reinterpret_cast<float2*>(Cw + (size_t)r1 * 64 + col) = v;
            }
        }
    }
}

// ================= layer-2 GEMM: tf32 mma (K=64, M=40 dual) =================
#define BM2 128
#define APAD3 20
#define BPW 88
__global__ __launch_bounds__(256, 2)
void k_gemm2_mma(const float* __restrict__ A,
                 const float* __restrict__ W1, const float* __restrict__ b1,
                 const float* __restrict__ W2, const float* __restrict__ b2,
                 float* __restrict__ C1, float* __restrict__ C2) {
    __shared__ float As[2][BM2 * APAD3];
    __shared__ float Bs[2][BK * BPW];

    const int tid = threadIdx.x;
    const int lane = tid & 31, warp = tid >> 5;
    const int wr = warp & 3, wc = warp >> 2;
    const int g = lane >> 2, tg = lane & 3;
    const int row0 = blockIdx.x * BM2;

    float acc[2][5][4];
#pragma unroll
    for (int mi = 0; mi < 2; mi++)
#pragma unroll
        for (int ni = 0; ni < 5; ni++)
#pragma unroll
            for (int r = 0; r < 4; r++) acc[mi][ni][r] = 0.f;

    const int rA = tid >> 2, qA = tid & 3;
    const int rAg0 = min(row0 + rA, NN - 1);
    const int rAg1 = min(row0 + rA + 64, NN - 1);
    const float* gA0 = A + (size_t)rAg0 * FF1 + qA * 4;
    const float* gA1 = A + (size_t)rAg1 * FF1 + qA * 4;
    const int sAoff0 = rA * APAD3 + qA * 4;
    const int sAoff1 = (rA + 64) * APAD3 + qA * 4;

    const int i0 = tid;
    const int kB0 = i0 / 20, c40 = i0 % 20;
    const int i1 = 256 + tid;
    const int kB1 = i1 / 20, c41 = i1 % 20;
    const int cB0 = c40 * 4, cB1 = c41 * 4;
    const float* gB0 = (cB0 < 40) ? (W1 + kB0 * 40 + cB0) : (W2 + kB0 * 40 + cB0 - 40);
    const float* gB1 = (cB1 < 40) ? (W1 + kB1 * 40 + cB1) : (W2 + kB1 * 40 + cB1 - 40);
    const int sB0 = kB0 * BPW + cB0;
    const int sB1 = kB1 * BPW + cB1;

    auto issue = [&](int it) {
        const int buf = it & 1;
        const int kc = it * BK;
        cp_async16(&As[buf][sAoff0], gA0 + kc);
        cp_async16(&As[buf][sAoff1], gA1 + kc);
        cp_async16(&Bs[buf][sB0], gB0 + kc * 40);
        if (tid < 64) cp_async16(&Bs[buf][sB1], gB1 + kc * 40);
        cp_commit();
    };

    const int NITER = FF1 / BK;   // 4
    issue(0);
    for (int it = 0; it < NITER; it++) {
        cp_wait0();
        __syncthreads();
        if (it + 1 < NITER) issue(it + 1);
        const int buf = it & 1;

#pragma unroll
        for (int ks = 0; ks < 2; ks++) {
            const int k0 = ks * 8;
            unsigned afr[2][4], bfr[5][2];
#pragma unroll
            for (int mi = 0; mi < 2; mi++) {
                const int base = wr * 32 + mi * 16;
                afr[mi][0] = f2tf32(As[buf][(base + g) * APAD3 + k0 + tg]);
                afr[mi][1] = f2tf32(As[buf][(base + g + 8) * APAD3 + k0 + tg]);
                afr[mi][2] = f2tf32(As[buf][(base + g) * APAD3 + k0 + tg + 4]);
                afr[mi][3] = f2tf32(As[buf][(base + g + 8) * APAD3 + k0 + tg + 4]);
            }
#pragma unroll
            for (int ni = 0; ni < 5; ni++) {
                const int col = wc * 40 + ni * 8 + g;
                bfr[ni][0] = f2tf32(Bs[buf][(k0 + tg) * BPW + col]);
                bfr[ni][1] = f2tf32(Bs[buf][(k0 + tg + 4) * BPW + col]);
            }
#pragma unroll
            for (int mi = 0; mi < 2; mi++)
#pragma unroll
                for (int ni = 0; ni < 5; ni++)
                    mma_tf32(acc[mi][ni], afr[mi], bfr[ni]);
        }
    }

    float* Cw = (wc == 0) ? C1 : C2;
    const float* bw = (wc == 0) ? b1 : b2;
#pragma unroll
    for (int mi = 0; mi < 2; mi++) {
#pragma unroll
        for (int ni = 0; ni < 5; ni++) {
            const int col = ni * 8 + 2 * tg;
            const float bb0 = __ldg(bw + col), bb1 = __ldg(bw + col + 1);
            const int r0 = row0 + wr * 32 + mi * 16 + g;
            const int r1 = r0 + 8;
            if (r0 < NN) {
                float2 v = make_float2(acc[mi][ni][0] + bb0, acc[mi][ni][1] + bb1);
                *reinterpret_cast<float2*>(Cw + (size_t)r0 * 40 + col) = v;
            }
            if (r1 < NN) {
                float2 v = make_float2(acc[mi][ni][2] + bb0, acc[mi][ni][3] + bb1);
                *reinterpret_cast<float2*>(Cw + (size_t)r1 * 40 + col) = v;
            }
        }
    }
}

// ========== fused layer-1 edge pass: 16 threads/edge, one float4 each ==========
__global__ __launch_bounds__(256)
void k_edge_agg1(const float* __restrict__ hs, const float* __restrict__ hd,
                 const float* __restrict__ attn,
                 const int* __restrict__ src, const int* __restrict__ dst,
                 float* __restrict__ s, float* __restrict__ acc) {
    int idx = blockIdx.x * blockDim.x + threadIdx.x;   // EE*16 exact
    int e = idx >> 4, j = idx & 15;                    // j: feature quad 0..15
    int lane = threadIdx.x & 31;
    int sn = __ldg(src + e), tn = __ldg(dst + e);

    float4 a = *reinterpret_cast<const float4*>(hs + (size_t)sn * 64 + j * 4);
    float4 b = *reinterpret_cast<const float4*>(hd + (size_t)tn * 64 + j * 4);
    float4 w = __ldg(reinterpret_cast<const float4*>(attn + j * 4));

    float part, x;
    x = a.x + b.x; part = (x > 0.f ? x : 0.2f * x) * w.x;
    x = a.y + b.y; part = fmaf((x > 0.f ? x : 0.2f * x), w.y, part);
    x = a.z + b.z; part = fmaf((x > 0.f ? x : 0.2f * x), w.z, part);
    x = a.w + b.w; part = fmaf((x > 0.f ? x : 0.2f * x), w.w, part);
    part += __shfl_xor_sync(0xffffffffu, part, 1);     // pair j, j^1 = same head
    float p = __expf(part);

    redv4(acc + (size_t)tn * 64 + j * 4, p * a.x, p * a.y, p * a.z, p * a.w);

    int base = lane & ~7;
    float v0 = __shfl_sync(0xffffffffu, p, base);
    float v1 = __shfl_sync(0xffffffffu, p, base + 2);
    float v2 = __shfl_sync(0xffffffffu, p, base + 4);
    float v3 = __shfl_sync(0xffffffffu, p, base + 6);
    if ((j & 7) == 0)
        redv4(s + (size_t)tn * 8 + (j >> 1), v0, v1, v2, v3);
}

// ---- scale1: h1 = elu(acc / (s + eps)) ----
__global__ void k_scale1(float* __restrict__ acc, const float* __restrict__ s) {
    int i = blockIdx.x * blockDim.x + threadIdx.x;
    if (i >= NN * 16) return;
    int t = i >> 4, q = i & 15;
    float inv = 1.f / (__ldg(s + t * 8 + (q >> 1)) + 1e-9f);
    float4 v = *reinterpret_cast<float4*>(acc + (size_t)t * 64 + q * 4);
    v.x *= inv; v.y *= inv; v.z *= inv; v.w *= inv;
    v.x = v.x > 0.f ? v.x : (__expf(v.x) - 1.f);
    v.y = v.y > 0.f ? v.y : (__expf(v.y) - 1.f);
    v.z = v.z > 0.f ? v.z : (__expf(v.z) - 1.f);
    v.w = v.w > 0.f ? v.w : (__expf(v.w) - 1.f);
    *reinterpret_cast<float4*>(acc + (size_t)t * 64 + q * 4) = v;
}

// ========== fused layer-2 edge pass: 8 threads/edge (R8 formulation) ==========
__global__ __launch_bounds__(256)
void k_edge_agg2(const float* __restrict__ hs, const float* __restrict__ hd,
                 const float* __restrict__ attn,
                 const int* __restrict__ src, const int* __restrict__ dst,
                 float* __restrict__ s, float* __restrict__ out) {
    int idx = blockIdx.x * blockDim.x + threadIdx.x;   // EE*8 exact
    int e = idx >> 3, j = idx & 7;
    int sn = __ldg(src + e), tn = __ldg(dst + e);

    float4 av[2], bv[2], wv[2];
    bool act2 = (j < 2);
    av[0] = *reinterpret_cast<const float4*>(hs + (size_t)sn * 40 + j * 4);
    bv[0] = *reinterpret_cast<const float4*>(hd + (size_t)tn * 40 + j * 4);
    wv[0] = __ldg(reinterpret_cast<const float4*>(attn + j * 4));
    if (act2) {
        av[1] = *reinterpret_cast<const float4*>(hs + (size_t)sn * 40 + (j + 8) * 4);
        bv[1] = *reinterpret_cast<const float4*>(hd + (size_t)tn * 40 + (j + 8) * 4);
        wv[1] = __ldg(reinterpret_cast<const float4*>(attn + (j + 8) * 4));
    }

    float part = 0.f, x;
    x = av[0].x + bv[0].x; part = fmaf((x > 0.f ? x : 0.2f * x), wv[0].x, part);
    x = av[0].y + bv[0].y; part = fmaf((x > 0.f ? x : 0.2f * x), wv[0].y, part);
    x = av[0].z + bv[0].z; part = fmaf((x > 0.f ? x : 0.2f * x), wv[0].z, part);
    x = av[0].w + bv[0].w; part = fmaf((x > 0.f ? x : 0.2f * x), wv[0].w, part);
    if (act2) {
        x = av[1].x + bv[1].x; part = fmaf((x > 0.f ? x : 0.2f * x), wv[1].x, part);
        x = av[1].y + bv[1].y; part = fmaf((x > 0.f ? x : 0.2f * x), wv[1].y, part);
        x = av[1].z + bv[1].z; part = fmaf((x > 0.f ? x : 0.2f * x), wv[1].z, part);
        x = av[1].w + bv[1].w; part = fmaf((x > 0.f ? x : 0.2f * x), wv[1].w, part);
    }
    part += __shfl_xor_sync(0xffffffffu, part, 4);
    part += __shfl_xor_sync(0xffffffffu, part, 2);
    part += __shfl_xor_sync(0xffffffffu, part, 1);
    float p = __expf(part);

    float* o = out + (size_t)tn * 40;
    redv4(o + j * 4, p * av[0].x, p * av[0].y, p * av[0].z, p * av[0].w);
    if (act2)
        redv4(o + (j + 8) * 4, p * av[1].x, p * av[1].y, p * av[1].z, p * av[1].w);
    if (j == 0)
        red1(s + tn, p);
}

// ---- scale2: out = acc / (s + eps) ----
__global__ void k_scale2(float* __restrict__ out, const float* __restrict__ s) {
    int i = blockIdx.x * blockDim.x + threadIdx.x;
    if (i >= NN * 10) return;
    int t = i / 10, q = i - t * 10;
    float inv = 1.f / (__ldg(s + t) + 1e-9f);
    float4 v = *reinterpret_cast<float4*>(out + (size_t)t * 40 + q * 4);
    v.x *= inv; v.y *= inv; v.z *= inv; v.w *= inv;
    *reinterpret_cast<float4*>(out + (size_t)t * 40 + q * 4) = v;
}

// ================= launch =================
extern "C" void kernel_launch(void* const* d_in, const int* in_sizes, int n_in,
                              void* d_out, int out_size) {
    const float* x   = (const float*)d_in[0];
    const int*   src = (const int*)d_in[1];
    const int*   dst = (const int*)d_in[2];
    const float* W1s = (const float*)d_in[3];
    const float* b1s = (const float*)d_in[4];
    const float* W1d = (const float*)d_in[5];
    const float* b1d = (const float*)d_in[6];
    const float* a1  = (const float*)d_in[7];
    const float* W2s = (const float*)d_in[8];
    const float* b2s = (const float*)d_in[9];
    const float* W2d = (const float*)d_in[10];
    const float* b2d = (const float*)d_in[11];
    const float* a2  = (const float*)d_in[12];
    float* out = (float*)d_out;

    float *hs1, *hd1, *s1, *h1, *hs2, *hd2, *s2;
    cudaGetSymbolAddress((void**)&hs1, g_hs1);
    cudaGetSymbolAddress((void**)&hd1, g_hd1);
    cudaGetSymbolAddress((void**)&s1,  g_s1);
    cudaGetSymbolAddress((void**)&h1,  g_h1);
    cudaGetSymbolAddress((void**)&hs2, g_hs2);
    cudaGetSymbolAddress((void**)&hd2, g_hd2);
    cudaGetSymbolAddress((void**)&s2,  g_s2);

    const int T = 256;

    // #1: zero h1+s1 ; #2: gemm1 ; #3: zero s2+out ; #4: edge_agg1 (profiled)
    k_zero2<<<(NN * FF1 + T - 1) / T, T>>>(h1, NN * FF1, s1, NN * 8);
    k_gemm1_mma<<<(NN + BM - 1) / BM, 256>>>(x, W1s, b1s, W1d, b1d, hs1, hd1);
    k_zero2<<<(NN * DD2 + T - 1) / T, T>>>(out, NN * DD2, s2, NN);
    k_edge_agg1<<<EE * 16 / T, T>>>(hs1, hd1, a1, src, dst, s1, h1);         // #4
    k_scale1<<<(NN * 16 + T - 1) / T, T>>>(h1, s1);

    // ---- layer 2 ----
    k_gemm2_mma<<<(NN + BM2 - 1) / BM2, 256>>>(h1, W2s, b2s, W2d, b2d, hs2, hd2);
    k_edge_agg2<<<EE * 8 / T, T>>>(hs2, hd2, a2, src, dst, s2, out);
    k_scale2<<<(NN * 10 + T - 1) / T, T>>>(out, s2);
}

// round 14
// speedup vs baseline: 1.0434x; 1.0184x over previous
#include <cuda_runtime.h>
#include <math.h>

#define NN 100000
#define EE 1600000
#define F_IN 512
#define FF1 64
#define DD2 40

// ---------------- scratch ----------------
__device__ float g_hs1[NN * FF1];
__device__ float g_hd1[NN * FF1];
__device__ float g_s1[NN * 8];
__device__ float g_h1[NN * FF1];
__device__ float g_hs2[NN * DD2];
__device__ float g_hd2[NN * DD2];
__device__ float g_s2[NN];
__device__ float g_w1r[F_IN * 128];   // [k][c], c<64: W1s, else W1d (tf32-rounded)
__device__ float g_w2r[FF1 * 80];     // [k][c], c<40: W2s, else W2d (tf32-rounded)

// ---------------- PTX helpers ----------------
__device__ __forceinline__ unsigned f2tf32(float f) {
    unsigned u;
    asm("cvt.rna.tf32.f32 %0, %1;" : "=r"(u) : "f"(f));
    return u;
}
__device__ __forceinline__ void redv4(float* addr, float a, float b, float c, float d) {
    asm volatile("red.global.add.v4.f32 [%0], {%1,%2,%3,%4};"
                 :: "l"(addr), "f"(a), "f"(b), "f"(c), "f"(d) : "memory");
}
__device__ __forceinline__ void red1(float* addr, float a) {
    asm volatile("red.global.add.f32 [%0], %1;" :: "l"(addr), "f"(a) : "memory");
}
__device__ __forceinline__ void mma_tf32(float* acc, const unsigned* a, const unsigned* b) {
    asm volatile(
        "mma.sync.aligned.m16n8k8.row.col.f32.tf32.tf32.f32 "
        "{%0,%1,%2,%3}, {%4,%5,%6,%7}, {%8,%9}, {%0,%1,%2,%3};"
        : "+f"(acc[0]), "+f"(acc[1]), "+f"(acc[2]), "+f"(acc[3])
        : "r"(a[0]), "r"(a[1]), "r"(a[2]), "r"(a[3]), "r"(b[0]), "r"(b[1]));
}
__device__ __forceinline__ void cp_async16(void* smem_dst, const void* gsrc) {
    unsigned saddr = (unsigned)__cvta_generic_to_shared(smem_dst);
    asm volatile("cp.async.cg.shared.global [%0], [%1], 16;" :: "r"(saddr), "l"(gsrc));
}
__device__ __forceinline__ void cp_commit() { asm volatile("cp.async.commit_group;"); }
__device__ __forceinline__ void cp_wait0() { asm volatile("cp.async.wait_group 0;"); }

// ---------------- zero / prep kernels ----------------
__global__ void k_zero1(float* a, int na) {
    int i = blockIdx.x * blockDim.x + threadIdx.x;
    if (i < na) a[i] = 0.f;
}
__global__ void k_zero2(float* a, int na, float* b, int nb) {
    int i = blockIdx.x * blockDim.x + threadIdx.x;
    if (i < na) a[i] = 0.f;
    if (i < nb) b[i] = 0.f;
}
// round all weights once (RNA), write combined layouts
__global__ void k_round(const float* __restrict__ W1s, const float* __restrict__ W1d,
                        const float* __restrict__ W2s, const float* __restrict__ W2d,
                        float* __restrict__ w1r, float* __restrict__ w2r) {
    int i = blockIdx.x * blockDim.x + threadIdx.x;
    if (i < F_IN * 128) {
        int k = i >> 7, c = i & 127;
        float w = (c < 64) ? W1s[k * 64 + c] : W1d[k * 64 + (c - 64)];
        w1r[i] = __uint_as_float(f2tf32(w));
    }
    if (i < FF1 * 80) {
        int k = i / 80, c = i - k * 80;
        float w = (c < 40) ? W2s[k * 40 + c] : W2d[k * 40 + (c - 40)];
        w2r[i] = __uint_as_float(f2tf32(w));
    }
}

// ================= layer-1 GEMM: tf32 mma, pre-rounded B, staged-rounded A =======
#define BM 64
#define BK 16
#define APAD2 20
#define BPAD2 136
__global__ __launch_bounds__(256, 3)
void k_gemm1_mma(const float* __restrict__ A, const float* __restrict__ w1r,
                 const float* __restrict__ b1, const float* __restrict__ b2,
                 float* __restrict__ C1, float* __restrict__ C2) {
    __shared__ unsigned As[2][BM * APAD2];
    __shared__ unsigned Bs[2][BK * BPAD2];

    const int tid = threadIdx.x;
    const int lane = tid & 31, warp = tid >> 5;
    const int wr = warp & 1, wc = warp >> 1;
    const int g = lane >> 2, tg = lane & 3;
    const int row0 = blockIdx.x * BM;

    float acc[2][4][4];
#pragma unroll
    for (int mi = 0; mi < 2; mi++)
#pragma unroll
        for (int ni = 0; ni < 4; ni++)
#pragma unroll
            for (int r = 0; r < 4; r++) acc[mi][ni][r] = 0.f;

    // A staging: 1 float4 per thread (64 rows x 16 k)
    const int rA = tid >> 2, qA = tid & 3;
    const int rAg = min(row0 + rA, NN - 1);
    const float* gA = A + (size_t)rAg * F_IN + qA * 4;
    const int sAoff = rA * APAD2 + qA * 4;

    // B staging via cp.async from pre-rounded combined weights [k][128]
    const int kB = tid >> 5;
    const int cB = (tid & 31) * 4;
    const float* gB = w1r + kB * 128 + cB;
    const int sBoff0 = kB * BPAD2 + cB;
    const int sBoff1 = (kB + 8) * BPAD2 + cB;

    float4 aR;
    auto issueB = [&](int it, int buf) {
        const int kc = it * BK;
        cp_async16(&Bs[buf][sBoff0], gB + kc * 128);
        cp_async16(&Bs[buf][sBoff1], gB + (kc + 8) * 128);
        cp_commit();
    };
    auto loadA = [&](int it) { aR = *reinterpret_cast<const float4*>(gA + it * BK); };
    auto storeA = [&](int buf) {
        uint4 u = make_uint4(f2tf32(aR.x), f2tf32(aR.y), f2tf32(aR.z), f2tf32(aR.w));
        *reinterpret_cast<uint4*>(&As[buf][sAoff]) = u;
    };

    const int NITER = F_IN / BK;   // 32
    issueB(0, 0);
    loadA(0);
    storeA(0);
    int buf = 0;
    for (int it = 0; it < NITER; it++) {
        cp_wait0();
        __syncthreads();
        if (it + 1 < NITER) { issueB(it + 1, buf ^ 1); loadA(it + 1); }

#pragma unroll
        for (int ks = 0; ks < 2; ks++) {
            const int k0 = ks * 8;
            unsigned afr[2][4], bfr[4][2];
#pragma unroll
            for (int mi = 0; mi < 2; mi++) {
                const int base = wr * 32 + mi * 16;
                afr[mi][0] = As[buf][(base + g) * APAD2 + k0 + tg];
                afr[mi][1] = As[buf][(base + g + 8) * APAD2 + k0 + tg];
                afr[mi][2] = As[buf][(base + g) * APAD2 + k0 + tg + 4];
                afr[mi][3] = As[buf][(base + g + 8) * APAD2 + k0 + tg + 4];
            }
#pragma unroll
            for (int ni = 0; ni < 4; ni++) {
                const int col = wc * 32 + ni * 8 + g;
                bfr[ni][0] = Bs[buf][(k0 + tg) * BPAD2 + col];
                bfr[ni][1] = Bs[buf][(k0 + tg + 4) * BPAD2 + col];
            }
#pragma unroll
            for (int mi = 0; mi < 2; mi++)
#pragma unroll
                for (int ni = 0; ni < 4; ni++)
                    mma_tf32(acc[mi][ni], afr[mi], bfr[ni]);
        }
        if (it + 1 < NITER) storeA(buf ^ 1);
        buf ^= 1;
    }

    float* Cw = (wc < 2) ? C1 : C2;
    const float* bw = (wc < 2) ? b1 : b2;
    const int cbase = (wc < 2) ? wc * 32 : (wc - 2) * 32;
#pragma unroll
    for (int mi = 0; mi < 2; mi++) {
#pragma unroll
        for (int ni = 0; ni < 4; ni++) {
            const int col = cbase + ni * 8 + 2 * tg;
            const float bb0 = __ldg(bw + col), bb1 = __ldg(bw + col + 1);
            const int r0 = row0 + wr * 32 + mi * 16 + g;
            const int r1 = r0 + 8;
            if (r0 < NN) {
                float2 v = make_float2(acc[mi][ni][0] + bb0, acc[mi][ni][1] + bb1);
                *reinterpret_cast<float2*>(Cw + (size_t)r0 * 64 + col) = v;
            }
            if (r1 < NN) {
                float2 v = make_float2(acc[mi][ni][2] + bb0, acc[mi][ni][3] + bb1);
                *reinterpret_cast<float2*>(Cw + (size_t)r1 * 64 + col) = v;
            }
        }
    }
}

// ================= layer-2 GEMM: tf32 mma, pre-rounded B, staged-rounded A =======
#define BM2 128
#define APAD3 20
#define BPW 88
__global__ __launch_bounds__(256, 2)
void k_gemm2_mma(const float* __restrict__ A, const float* __restrict__ w2r,
                 const float* __restrict__ b1, const float* __restrict__ b2,
                 float* __restrict__ C1, float* __restrict__ C2) {
    __shared__ unsigned As[2][BM2 * APAD3];
    __shared__ unsigned Bs[2][BK * BPW];

    const int tid = threadIdx.x;
    const int lane = tid & 31, warp = tid >> 5;
    const int wr = warp & 3, wc = warp >> 2;
    const int g = lane >> 2, tg = lane & 3;
    const int row0 = blockIdx.x * BM2;

    float acc[2][5][4];
#pragma unroll
    for (int mi = 0; mi < 2; mi++)
#pragma unroll
        for (int ni = 0; ni < 5; ni++)
#pragma unroll
            for (int r = 0; r < 4; r++) acc[mi][ni][r] = 0.f;

    // A staging: 2 float4 per thread (128 rows x 16 k)
    const int rA = tid >> 2, qA = tid & 3;
    const int rAg0 = min(row0 + rA, NN - 1);
    const int rAg1 = min(row0 + rA + 64, NN - 1);
    const float* gA0 = A + (size_t)rAg0 * FF1 + qA * 4;
    const float* gA1 = A + (size_t)rAg1 * FF1 + qA * 4;
    const int sAoff0 = rA * APAD3 + qA * 4;
    const int sAoff1 = (rA + 64) * APAD3 + qA * 4;

    // B staging via cp.async from pre-rounded [k][80]
    const int i0 = tid;
    const int kB0 = i0 / 20, c40 = i0 % 20;
    const int i1 = 256 + tid;
    const int kB1 = i1 / 20, c41 = i1 % 20;
    const int cB0 = c40 * 4, cB1 = c41 * 4;
    const float* gB0 = w2r + kB0 * 80 + cB0;
    const float* gB1 = w2r + kB1 * 80 + cB1;
    const int sB0 = kB0 * BPW + cB0;
    const int sB1 = kB1 * BPW + cB1;

    float4 aR0, aR1;
    auto issueB = [&](int it, int buf) {
        const int kc = it * BK;
        cp_async16(&Bs[buf][sB0], gB0 + kc * 80);
        if (tid < 64) cp_async16(&Bs[buf][sB1], gB1 + kc * 80);
        cp_commit();
    };
    auto loadA = [&](int it) {
        aR0 = *reinterpret_cast<const float4*>(gA0 + it * BK);
        aR1 = *reinterpret_cast<const float4*>(gA1 + it * BK);
    };
    auto storeA = [&](int buf) {
        uint4 u0 = make_uint4(f2tf32(aR0.x), f2tf32(aR0.y), f2tf32(aR0.z), f2tf32(aR0.w));
        uint4 u1 = make_uint4(f2tf32(aR1.x), f2tf32(aR1.y), f2tf32(aR1.z), f2tf32(aR1.w));
        *reinterpret_cast<uint4*>(&As[buf][sAoff0]) = u0;
        *reinterpret_cast<uint4*>(&As[buf][sAoff1]) = u1;
    };

    const int NITER = FF1 / BK;   // 4
    issueB(0, 0);
    loadA(0);
    storeA(0);
    int buf = 0;
    for (int it = 0; it < NITER; it++) {
        cp_wait0();
        __syncthreads();
        if (it + 1 < NITER) { issueB(it + 1, buf ^ 1); loadA(it + 1); }

#pragma unroll
        for (int ks = 0; ks < 2; ks++) {
            const int k0 = ks * 8;
            unsigned afr[2][4], bfr[5][2];
#pragma unroll
            for (int mi = 0; mi < 2; mi++) {
                const int base = wr * 32 + mi * 16;
                afr[mi][0] = As[buf][(base + g) * APAD3 + k0 + tg];
                afr[mi][1] = As[buf][(base + g + 8) * APAD3 + k0 + tg];
                afr[mi][2] = As[buf][(base + g) * APAD3 + k0 + tg + 4];
                afr[mi][3] = As[buf][(base + g + 8) * APAD3 + k0 + tg + 4];
            }
#pragma unroll
            for (int ni = 0; ni < 5; ni++) {
                const int col = wc * 40 + ni * 8 + g;
                bfr[ni][0] = Bs[buf][(k0 + tg) * BPW + col];
                bfr[ni][1] = Bs[buf][(k0 + tg + 4) * BPW + col];
            }
#pragma unroll
            for (int mi = 0; mi < 2; mi++)
#pragma unroll
                for (int ni = 0; ni < 5; ni++)
                    mma_tf32(acc[mi][ni], afr[mi], bfr[ni]);
        }
        if (it + 1 < NITER) storeA(buf ^ 1);
        buf ^= 1;
    }

    float* Cw = (wc == 0) ? C1 : C2;
    const float* bw = (wc == 0) ? b1 : b2;
#pragma unroll
    for (int mi = 0; mi < 2; mi++) {
#pragma unroll
        for (int ni = 0; ni < 5; ni++) {
            const int col = ni * 8 + 2 * tg;
            const float bb0 = __ldg(bw + col), bb1 = __ldg(bw + col + 1);
            const int r0 = row0 + wr * 32 + mi * 16 + g;
            const int r1 = r0 + 8;
            if (r0 < NN) {
                float2 v = make_float2(acc[mi][ni][0] + bb0, acc[mi][ni][1] + bb1);
                *reinterpret_cast<float2*>(Cw + (size_t)r0 * 40 + col) = v;
            }
            if (r1 < NN) {
                float2 v = make_float2(acc[mi][ni][2] + bb0, acc[mi][ni][3] + bb1);
                *reinterpret_cast<float2*>(Cw + (size_t)r1 * 40 + col) = v;
            }
        }
    }
}

// ========== fused layer-1 edge pass: 16 threads/edge ==========
__global__ __launch_bounds__(256)
void k_edge_agg1(const float* __restrict__ hs, const float* __restrict__ hd,
                 const float* __restrict__ attn,
                 const int* __restrict__ src, const int* __restrict__ dst,
                 float* __restrict__ s, float* __restrict__ acc) {
    int idx = blockIdx.x * blockDim.x + threadIdx.x;   // EE*16 exact
    int e = idx >> 4, j = idx & 15;
    int lane = threadIdx.x & 31;
    int sn = __ldg(src + e), tn = __ldg(dst + e);

    float4 a = *reinterpret_cast<const float4*>(hs + (size_t)sn * 64 + j * 4);
    float4 b = *reinterpret_cast<const float4*>(hd + (size_t)tn * 64 + j * 4);
    float4 w = __ldg(reinterpret_cast<const float4*>(attn + j * 4));

    float part, x;
    x = a.x + b.x; part = (x > 0.f ? x : 0.2f * x) * w.x;
    x = a.y + b.y; part = fmaf((x > 0.f ? x : 0.2f * x), w.y, part);
    x = a.z + b.z; part = fmaf((x > 0.f ? x : 0.2f * x), w.z, part);
    x = a.w + b.w; part = fmaf((x > 0.f ? x : 0.2f * x), w.w, part);
    part += __shfl_xor_sync(0xffffffffu, part, 1);
    float p = __expf(part);

    redv4(acc + (size_t)tn * 64 + j * 4, p * a.x, p * a.y, p * a.z, p * a.w);

    int base = lane & ~7;
    float v0 = __shfl_sync(0xffffffffu, p, base);
    float v1 = __shfl_sync(0xffffffffu, p, base + 2);
    float v2 = __shfl_sync(0xffffffffu, p, base + 4);
    float v3 = __shfl_sync(0xffffffffu, p, base + 6);
    if ((j & 7) == 0)
        redv4(s + (size_t)tn * 8 + (j >> 1), v0, v1, v2, v3);
}

// ---- scale1: h1 = elu(acc / (s + eps)) ----
__global__ void k_scale1(float* __restrict__ acc, const float* __restrict__ s) {
    int i = blockIdx.x * blockDim.x + threadIdx.x;
    if (i >= NN * 16) return;
    int t = i >> 4, q = i & 15;
    float inv = 1.f / (__ldg(s + t * 8 + (q >> 1)) + 1e-9f);
    float4 v = *reinterpret_cast<float4*>(acc + (size_t)t * 64 + q * 4);
    v.x *= inv; v.y *= inv; v.z *= inv; v.w *= inv;
    v.x = v.x > 0.f ? v.x : (__expf(v.x) - 1.f);
    v.y = v.y > 0.f ? v.y : (__expf(v.y) - 1.f);
    v.z = v.z > 0.f ? v.z : (__expf(v.z) - 1.f);
    v.w = v.w > 0.f ? v.w : (__expf(v.w) - 1.f);
    *reinterpret_cast<float4*>(acc + (size_t)t * 64 + q * 4) = v;
}

// ========== fused layer-2 edge pass: 8 threads/edge ==========
__global__ __launch_bounds__(256)
void k_edge_agg2(const float* __restrict__ hs, const float* __restrict__ hd,
                 const float* __restrict__ attn,
                 const int* __restrict__ src, const int* __restrict__ dst,
                 float* __restrict__ s, float* __restrict__ out) {
    int idx = blockIdx.x * blockDim.x + threadIdx.x;   // EE*8 exact
    int e = idx >> 3, j = idx & 7;
    int sn = __ldg(src + e), tn = __ldg(dst + e);

    float4 av[2], bv[2], wv[2];
    bool act2 = (j < 2);
    av[0] = *reinterpret_cast<const float4*>(hs + (size_t)sn * 40 + j * 4);
    bv[0] = *reinterpret_cast<const float4*>(hd + (size_t)tn * 40 + j * 4);
    wv[0] = __ldg(reinterpret_cast<const float4*>(attn + j * 4));
    if (act2) {
        av[1] = *reinterpret_cast<const float4*>(hs + (size_t)sn * 40 + (j + 8) * 4);
        bv[1] = *reinterpret_cast<const float4*>(hd + (size_t)tn * 40 + (j + 8) * 4);
        wv[1] = __ldg(reinterpret_cast<const float4*>(attn + (j + 8) * 4));
    }

    float part = 0.f, x;
    x = av[0].x + bv[0].x; part = fmaf((x > 0.f ? x : 0.2f * x), wv[0].x, part);
    x = av[0].y + bv[0].y; part = fmaf((x > 0.f ? x : 0.2f * x), wv[0].y, part);
    x = av[0].z + bv[0].z; part = fmaf((x > 0.f ? x : 0.2f * x), wv[0].z, part);
    x = av[0].w + bv[0].w; part = fmaf((x > 0.f ? x : 0.2f * x), wv[0].w, part);
    if (act2) {
        x = av[1].x + bv[1].x; part = fmaf((x > 0.f ? x : 0.2f * x), wv[1].x, part);
        x = av[1].y + bv[1].y; part = fmaf((x > 0.f ? x : 0.2f * x), wv[1].y, part);
        x = av[1].z + bv[1].z; part = fmaf((x > 0.f ? x : 0.2f * x), wv[1].z, part);
        x = av[1].w + bv[1].w; part = fmaf((x > 0.f ? x : 0.2f * x), wv[1].w, part);
    }
    part += __shfl_xor_sync(0xffffffffu, part, 4);
    part += __shfl_xor_sync(0xffffffffu, part, 2);
    part += __shfl_xor_sync(0xffffffffu, part, 1);
    float p = __expf(part);

    float* o = out + (size_t)tn * 40;
    redv4(o + j * 4, p * av[0].x, p * av[0].y, p * av[0].z, p * av[0].w);
    if (act2)
        redv4(o + (j + 8) * 4, p * av[1].x, p * av[1].y, p * av[1].z, p * av[1].w);
    if (j == 0)
        red1(s + tn, p);
}

// ---- scale2: out = acc / (s + eps) ----
__global__ void k_scale2(float* __restrict__ out, const float* __restrict__ s) {
    int i = blockIdx.x * blockDim.x + threadIdx.x;
    if (i >= NN * 10) return;
    int t = i / 10, q = i - t * 10;
    float inv = 1.f / (__ldg(s + t) + 1e-9f);
    float4 v = *reinterpret_cast<float4*>(out + (size_t)t * 40 + q * 4);
    v.x *= inv; v.y *= inv; v.z *= inv; v.w *= inv;
    *reinterpret_cast<float4*>(out + (size_t)t * 40 + q * 4) = v;
}

// ================= launch =================
extern "C" void kernel_launch(void* const* d_in, const int* in_sizes, int n_in,
                              void* d_out, int out_size) {
    const float* x   = (const float*)d_in[0];
    const int*   src = (const int*)d_in[1];
    const int*   dst = (const int*)d_in[2];
    const float* W1s = (const float*)d_in[3];
    const float* b1s = (const float*)d_in[4];
    const float* W1d = (const float*)d_in[5];
    const float* b1d = (const float*)d_in[6];
    const float* a1  = (const float*)d_in[7];
    const float* W2s = (const float*)d_in[8];
    const float* b2s = (const float*)d_in[9];
    const float* W2d = (const float*)d_in[10];
    const float* b2d = (const float*)d_in[11];
    const float* a2  = (const float*)d_in[12];
    float* out = (float*)d_out;

    float *hs1, *hd1, *s1, *h1, *hs2, *hd2, *s2, *w1r, *w2r;
    cudaGetSymbolAddress((void**)&hs1, g_hs1);
    cudaGetSymbolAddress((void**)&hd1, g_hd1);
    cudaGetSymbolAddress((void**)&s1,  g_s1);
    cudaGetSymbolAddress((void**)&h1,  g_h1);
    cudaGetSymbolAddress((void**)&hs2, g_hs2);
    cudaGetSymbolAddress((void**)&hd2, g_hd2);
    cudaGetSymbolAddress((void**)&s2,  g_s2);
    cudaGetSymbolAddress((void**)&w1r, g_w1r);
    cudaGetSymbolAddress((void**)&w2r, g_w2r);

    const int T = 256;

    // #1-3: zeros + weight prep ; #4: gemm1 (profiled)
    k_zero2<<<(NN * FF1 + T - 1) / T, T>>>(h1, NN * FF1, s1, NN * 8);
    k_zero2<<<(NN * DD2 + T - 1) / T, T>>>(out, NN * DD2, s2, NN);
    k_round<<<(F_IN * 128 + T - 1) / T, T>>>(W1s, W1d, W2s, W2d, w1r, w2r);
    k_gemm1_mma<<<(NN + BM - 1) / BM, 256>>>(x, w1r, b1s, b1d, hs1, hd1);    // #4
    k_edge_agg1<<<EE * 16 / T, T>>>(hs1, hd1, a1, src, dst, s1, h1);
    k_scale1<<<(NN * 16 + T - 1) / T, T>>>(h1, s1);

    // ---- layer 2 ----
    k_gemm2_mma<<<(NN + BM2 - 1) / BM2, 256>>>(h1, w2r, b2s, b2d, hs2, hd2);
    k_edge_agg2<<<EE * 8 / T, T>>>(hs2, hd2, a2, src, dst, s2, out);
    k_scale2<<<(NN * 10 + T - 1) / T, T>>>(out, s2);
}

// round 16
// speedup vs baseline: 1.0476x; 1.0040x over previous
#include <cuda_runtime.h>
#include <math.h>

#define NN 100000
#define EE 1600000
#define F_IN 512
#define FF1 64
#define DD2 40

// ---------------- scratch ----------------
__device__ float g_hs1[NN * FF1];
__device__ float g_hd1[NN * FF1];
__device__ float g_s1[NN * 8];
__device__ float g_h1[NN * FF1];
__device__ float g_hs2[NN * DD2];
__device__ float g_hd2[NN * DD2];
__device__ float g_s2[NN];
__device__ float g_w1r[F_IN * 128];   // [k][c], c<64: W1s, else W1d (tf32-rounded)
__device__ float g_w2r[FF1 * 80];     // [k][c], c<40: W2s, else W2d (tf32-rounded)

// ---------------- PTX helpers ----------------
__device__ __forceinline__ unsigned f2tf32(float f) {
    unsigned u;
    asm("cvt.rna.tf32.f32 %0, %1;" : "=r"(u) : "f"(f));
    return u;
}
__device__ __forceinline__ void redv4(float* addr, float a, float b, float c, float d) {
    asm volatile("red.global.add.v4.f32 [%0], {%1,%2,%3,%4};"
                 :: "l"(addr), "f"(a), "f"(b), "f"(c), "f"(d) : "memory");
}
__device__ __forceinline__ void red1(float* addr, float a) {
    asm volatile("red.global.add.f32 [%0], %1;" :: "l"(addr), "f"(a) : "memory");
}
__device__ __forceinline__ void mma_tf32(float* acc, const unsigned* a, const unsigned* b) {
    asm volatile(
        "mma.sync.aligned.m16n8k8.row.col.f32.tf32.tf32.f32 "
        "{%0,%1,%2,%3}, {%4,%5,%6,%7}, {%8,%9}, {%0,%1,%2,%3};"
        : "+f"(acc[0]), "+f"(acc[1]), "+f"(acc[2]), "+f"(acc[3])
        : "r"(a[0]), "r"(a[1]), "r"(a[2]), "r"(a[3]), "r"(b[0]), "r"(b[1]));
}
__device__ __forceinline__ void cp_async16(void* smem_dst, const void* gsrc) {
    unsigned saddr = (unsigned)__cvta_generic_to_shared(smem_dst);
    asm volatile("cp.async.cg.shared.global [%0], [%1], 16;" :: "r"(saddr), "l"(gsrc));
}
__device__ __forceinline__ void cp_commit() { asm volatile("cp.async.commit_group;"); }
__device__ __forceinline__ void cp_wait0() { asm volatile("cp.async.wait_group 0;"); }

__device__ __forceinline__ float elux(float v) {
    return v > 0.f ? v : (__expf(v) - 1.f);
}

// ---------------- zero / prep kernels ----------------
__global__ void k_zero2(float* a, int na, float* b, int nb) {
    int i = blockIdx.x * blockDim.x + threadIdx.x;
    if (i < na) a[i] = 0.f;
    if (i < nb) b[i] = 0.f;
}
// round all weights once (RNA), write combined layouts
__global__ void k_round(const float* __restrict__ W1s, const float* __restrict__ W1d,
                        const float* __restrict__ W2s, const float* __restrict__ W2d,
                        float* __restrict__ w1r, float* __restrict__ w2r) {
    int i = blockIdx.x * blockDim.x + threadIdx.x;
    if (i < F_IN * 128) {
        int k = i >> 7, c = i & 127;
        float w = (c < 64) ? W1s[k * 64 + c] : W1d[k * 64 + (c - 64)];
        w1r[i] = __uint_as_float(f2tf32(w));
    }
    if (i < FF1 * 80) {
        int k = i / 80, c = i - k * 80;
        float w = (c < 40) ? W2s[k * 40 + c] : W2d[k * 40 + (c - 40)];
        w2r[i] = __uint_as_float(f2tf32(w));
    }
}

// ================= layer-1 GEMM: tf32 mma, pre-rounded B, staged-rounded A =======
#define BM 64
#define BK 16
#define APAD2 20
#define BPAD2 136
__global__ __launch_bounds__(256, 3)
void k_gemm1_mma(const float* __restrict__ A, const float* __restrict__ w1r,
                 const float* __restrict__ b1, const float* __restrict__ b2,
                 float* __restrict__ C1, float* __restrict__ C2) {
    __shared__ unsigned As[2][BM * APAD2];
    __shared__ unsigned Bs[2][BK * BPAD2];

    const int tid = threadIdx.x;
    const int lane = tid & 31, warp = tid >> 5;
    const int wr = warp & 1, wc = warp >> 1;
    const int g = lane >> 2, tg = lane & 3;
    const int row0 = blockIdx.x * BM;

    float acc[2][4][4];
#pragma unroll
    for (int mi = 0; mi < 2; mi++)
#pragma unroll
        for (int ni = 0; ni < 4; ni++)
#pragma unroll
            for (int r = 0; r < 4; r++) acc[mi][ni][r] = 0.f;

    const int rA = tid >> 2, qA = tid & 3;
    const int rAg = min(row0 + rA, NN - 1);
    const float* gA = A + (size_t)rAg * F_IN + qA * 4;
    const int sAoff = rA * APAD2 + qA * 4;

    const int kB = tid >> 5;
    const int cB = (tid & 31) * 4;
    const float* gB = w1r + kB * 128 + cB;
    const int sBoff0 = kB * BPAD2 + cB;
    const int sBoff1 = (kB + 8) * BPAD2 + cB;

    float4 aR;
    auto issueB = [&](int it, int buf) {
        const int kc = it * BK;
        cp_async16(&Bs[buf][sBoff0], gB + kc * 128);
        cp_async16(&Bs[buf][sBoff1], gB + (kc + 8) * 128);
        cp_commit();
    };
    auto loadA = [&](int it) { aR = *reinterpret_cast<const float4*>(gA + it * BK); };
    auto storeA = [&](int buf) {
        uint4 u = make_uint4(f2tf32(aR.x), f2tf32(aR.y), f2tf32(aR.z), f2tf32(aR.w));
        *reinterpret_cast<uint4*>(&As[buf][sAoff]) = u;
    };

    const int NITER = F_IN / BK;   // 32
    issueB(0, 0);
    loadA(0);
    storeA(0);
    int buf = 0;
    for (int it = 0; it < NITER; it++) {
        cp_wait0();
        __syncthreads();
        if (it + 1 < NITER) { issueB(it + 1, buf ^ 1); loadA(it + 1); }

#pragma unroll
        for (int ks = 0; ks < 2; ks++) {
            const int k0 = ks * 8;
            unsigned afr[2][4], bfr[4][2];
#pragma unroll
            for (int mi = 0; mi < 2; mi++) {
                const int base = wr * 32 + mi * 16;
                afr[mi][0] = As[buf][(base + g) * APAD2 + k0 + tg];
                afr[mi][1] = As[buf][(base + g + 8) * APAD2 + k0 + tg];
                afr[mi][2] = As[buf][(base + g) * APAD2 + k0 + tg + 4];
                afr[mi][3] = As[buf][(base + g + 8) * APAD2 + k0 + tg + 4];
            }
#pragma unroll
            for (int ni = 0; ni < 4; ni++) {
                const int col = wc * 32 + ni * 8 + g;
                bfr[ni][0] = Bs[buf][(k0 + tg) * BPAD2 + col];
                bfr[ni][1] = Bs[buf][(k0 + tg + 4) * BPAD2 + col];
            }
#pragma unroll
            for (int mi = 0; mi < 2; mi++)
#pragma unroll
                for (int ni = 0; ni < 4; ni++)
                    mma_tf32(acc[mi][ni], afr[mi], bfr[ni]);
        }
        if (it + 1 < NITER) storeA(buf ^ 1);
        buf ^= 1;
    }

    float* Cw = (wc < 2) ? C1 : C2;
    const float* bw = (wc < 2) ? b1 : b2;
    const int cbase = (wc < 2) ? wc * 32 : (wc - 2) * 32;
#pragma unroll
    for (int mi = 0; mi < 2; mi++) {
#pragma unroll
        for (int ni = 0; ni < 4; ni++) {
            const int col = cbase + ni * 8 + 2 * tg;
            const float bb0 = __ldg(bw + col), bb1 = __ldg(bw + col + 1);
            const int r0 = row0 + wr * 32 + mi * 16 + g;
            const int r1 = r0 + 8;
            if (r0 < NN) {
                float2 v = make_float2(acc[mi][ni][0] + bb0, acc[mi][ni][1] + bb1);
                *reinterpret_cast<float2*>(Cw + (size_t)r0 * 64 + col) = v;
            }
            if (r1 < NN) {
                float2 v = make_float2(acc[mi][ni][2] + bb0, acc[mi][ni][3] + bb1);
                *reinterpret_cast<float2*>(Cw + (size_t)r1 * 64 + col) = v;
            }
        }
    }
}

// ====== layer-2 GEMM: tf32 mma, FUSED softmax-normalize + ELU on A staging ======
// A element = elu( h1_acc[r][k] / (s1[r][k>>3] + eps) ), then RNA-round.
#define BM2 128
#define APAD3 20
#define BPW 88
__global__ __launch_bounds__(256, 2)
void k_gemm2_mma(const float* __restrict__ Araw, const float* __restrict__ s1,
                 const float* __restrict__ w2r,
                 const float* __restrict__ b1, const float* __restrict__ b2,
                 float* __restrict__ C1, float* __restrict__ C2) {
    __shared__ unsigned As[2][BM2 * APAD3];
    __shared__ unsigned Bs[2][BK * BPW];

    const int tid = threadIdx.x;
    const int lane = tid & 31, warp = tid >> 5;
    const int wr = warp & 3, wc = warp >> 2;
    const int g = lane >> 2, tg = lane & 3;
    const int row0 = blockIdx.x * BM2;

    float acc[2][5][4];
#pragma unroll
    for (int mi = 0; mi < 2; mi++)
#pragma unroll
        for (int ni = 0; ni < 5; ni++)
#pragma unroll
            for (int r = 0; r < 4; r++) acc[mi][ni][r] = 0.f;

    const int rA = tid >> 2, qA = tid & 3;
    const int rAg0 = min(row0 + rA, NN - 1);
    const int rAg1 = min(row0 + rA + 64, NN - 1);
    const float* gA0 = Araw + (size_t)rAg0 * FF1 + qA * 4;
    const float* gA1 = Araw + (size_t)rAg1 * FF1 + qA * 4;
    const int sAoff0 = rA * APAD3 + qA * 4;
    const int sAoff1 = (rA + 64) * APAD3 + qA * 4;

    const int i0 = tid;
    const int kB0 = i0 / 20, c40 = i0 % 20;
    const int i1 = 256 + tid;
    const int kB1 = i1 / 20, c41 = i1 % 20;
    const int cB0 = c40 * 4, cB1 = c41 * 4;
    const float* gB0 = w2r + kB0 * 80 + cB0;
    const float* gB1 = w2r + kB1 * 80 + cB1;
    const int sB0 = kB0 * BPW + cB0;
    const int sB1 = kB1 * BPW + cB1;

    float4 aR0, aR1;
    float inv0, inv1;
    auto issueB = [&](int it, int buf) {
        const int kc = it * BK;
        cp_async16(&Bs[buf][sB0], gB0 + kc * 80);
        if (tid < 64) cp_async16(&Bs[buf][sB1], gB1 + kc * 80);
        cp_commit();
    };
    auto loadA = [&](int it) {
        aR0 = *reinterpret_cast<const float4*>(gA0 + it * BK);
        aR1 = *reinterpret_cast<const float4*>(gA1 + it * BK);
        const int head = (it * BK + qA * 4) >> 3;   // constant across the float4
        inv0 = 1.f / (__ldg(s1 + rAg0 * 8 + head) + 1e-9f);
        inv1 = 1.f / (__ldg(s1 + rAg1 * 8 + head) + 1e-9f);
    };
    auto storeA = [&](int buf) {
        uint4 u0 = make_uint4(f2tf32(elux(aR0.x * inv0)), f2tf32(elux(aR0.y * inv0)),
                              f2tf32(elux(aR0.z * inv0)), f2tf32(elux(aR0.w * inv0)));
        uint4 u1 = make_uint4(f2tf32(elux(aR1.x * inv1)), f2tf32(elux(aR1.y * inv1)),
                              f2tf32(elux(aR1.z * inv1)), f2tf32(elux(aR1.w * inv1)));
        *reinterpret_cast<uint4*>(&As[buf][sAoff0]) = u0;
        *reinterpret_cast<uint4*>(&As[buf][sAoff1]) = u1;
    };

    const int NITER = FF1 / BK;   // 4
    issueB(0, 0);
    loadA(0);
    storeA(0);
    int buf = 0;
    for (int it = 0; it < NITER; it++) {
        cp_wait0();
        __syncthreads();
        if (it + 1 < NITER) { issueB(it + 1, buf ^ 1); loadA(it + 1); }

#pragma unroll
        for (int ks = 0; ks < 2; ks++) {
            const int k0 = ks * 8;
            unsigned afr[2][4], bfr[5][2];
#pragma unroll
            for (int mi = 0; mi < 2; mi++) {
                const int base = wr * 32 + mi * 16;
                afr[mi][0] = As[buf][(base + g) * APAD3 + k0 + tg];
                afr[mi][1] = As[buf][(base + g + 8) * APAD3 + k0 + tg];
                afr[mi][2] = As[buf][(base + g) * APAD3 + k0 + tg + 4];
                afr[mi][3] = As[buf][(base + g + 8) * APAD3 + k0 + tg + 4];
            }
#pragma unroll
            for (int ni = 0; ni < 5; ni++) {
                const int col = wc * 40 + ni * 8 + g;
                bfr[ni][0] = Bs[buf][(k0 + tg) * BPW + col];
                bfr[ni][1] = Bs[buf][(k0 + tg + 4) * BPW + col];
            }
#pragma unroll
            for (int mi = 0; mi < 2; mi++)
#pragma unroll
                for (int ni = 0; ni < 5; ni++)
                    mma_tf32(acc[mi][ni], afr[mi], bfr[ni]);
        }
        if (it + 1 < NITER) storeA(buf ^ 1);
        buf ^= 1;
    }

    float* Cw = (wc == 0) ? C1 : C2;
    const float* bw = (wc == 0) ? b1 : b2;
#pragma unroll
    for (int mi = 0; mi < 2; mi++) {
#pragma unroll
        for (int ni = 0; ni < 5; ni++) {
            const int col = ni * 8 + 2 * tg;
            const float bb0 = __ldg(bw + col), bb1 = __ldg(bw + col + 1);
            const int r0 = row0 + wr * 32 + mi * 16 + g;
            const int r1 = r0 + 8;
            if (r0 < NN) {
                float2 v = make_float2(acc[mi][ni][0] + bb0, acc[mi][ni][1] + bb1);
                *reinterpret_cast<float2*>(Cw + (size_t)r0 * 40 + col) = v;
            }
            if (r1 < NN) {
                float2 v = make_float2(acc[mi][ni][2] + bb0, acc[mi][ni][3] + bb1);
                *reinterpret_cast<float2*>(Cw + (size_t)r1 * 40 + col) = v;
            }
        }
    }
}

// ========== fused layer-1 edge pass: 16 threads/edge ==========
__global__ __launch_bounds__(256)
void k_edge_agg1(const float* __restrict__ hs, const float* __restrict__ hd,
                 const float* __restrict__ attn,
                 const int* __restrict__ src, const int* __restrict__ dst,
                 float* __restrict__ s, float* __restrict__ acc) {
    int idx = blockIdx.x * blockDim.x + threadIdx.x;   // EE*16 exact
    int e = idx >> 4, j = idx & 15;
    int lane = threadIdx.x & 31;
    int sn = __ldg(src + e), tn = __ldg(dst + e);

    float4 a = *reinterpret_cast<const float4*>(hs + (size_t)sn * 64 + j * 4);
    float4 b = *reinterpret_cast<const float4*>(hd + (size_t)tn * 64 + j * 4);
    float4 w = __ldg(reinterpret_cast<const float4*>(attn + j * 4));

    float part, x;
    x = a.x + b.x; part = (x > 0.f ? x : 0.2f * x) * w.x;
    x = a.y + b.y; part = fmaf((x > 0.f ? x : 0.2f * x), w.y, part);
    x = a.z + b.z; part = fmaf((x > 0.f ? x : 0.2f * x), w.z, part);
    x = a.w + b.w; part = fmaf((x > 0.f ? x : 0.2f * x), w.w, part);
    part += __shfl_xor_sync(0xffffffffu, part, 1);
    float p = __expf(part);

    redv4(acc + (size_t)tn * 64 + j * 4, p * a.x, p * a.y, p * a.z, p * a.w);

    int base = lane & ~7;
    float v0 = __shfl_sync(0xffffffffu, p, base);
    float v1 = __shfl_sync(0xffffffffu, p, base + 2);
    float v2 = __shfl_sync(0xffffffffu, p, base + 4);
    float v3 = __shfl_sync(0xffffffffu, p, base + 6);
    if ((j & 7) == 0)
        redv4(s + (size_t)tn * 8 + (j >> 1), v0, v1, v2, v3);
}

// ========== fused layer-2 edge pass: 8 threads/edge ==========
__global__ __launch_bounds__(256)
void k_edge_agg2(const float* __restrict__ hs, const float* __restrict__ hd,
                 const float* __restrict__ attn,
                 const int* __restrict__ src, const int* __restrict__ dst,
                 float* __restrict__ s, float* __restrict__ out) {
    int idx = blockIdx.x * blockDim.x + threadIdx.x;   // EE*8 exact
    int e = idx >> 3, j = idx & 7;
    int sn = __ldg(src + e), tn = __ldg(dst + e);

    float4 av[2], bv[2], wv[2];
    bool act2 = (j < 2);
    av[0] = *reinterpret_cast<const float4*>(hs + (size_t)sn * 40 + j * 4);
    bv[0] = *reinterpret_cast<const float4*>(hd + (size_t)tn * 40 + j * 4);
    wv[0] = __ldg(reinterpret_cast<const float4*>(attn + j * 4));
    if (act2) {
        av[1] = *reinterpret_cast<const float4*>(hs + (size_t)sn * 40 + (j + 8) * 4);
        bv[1] = *reinterpret_cast<const float4*>(hd + (size_t)tn * 40 + (j + 8) * 4);
        wv[1] = __ldg(reinterpret_cast<const float4*>(attn + (j + 8) * 4));
    }

    float part = 0.f, x;
    x = av[0].x + bv[0].x; part = fmaf((x > 0.f ? x : 0.2f * x), wv[0].x, part);
    x = av[0].y + bv[0].y; part = fmaf((x > 0.f ? x : 0.2f * x), wv[0].y, part);
    x = av[0].z + bv[0].z; part = fmaf((x > 0.f ? x : 0.2f * x), wv[0].z, part);
    x = av[0].w + bv[0].w; part = fmaf((x > 0.f ? x : 0.2f * x), wv[0].w, part);
    if (act2) {
        x = av[1].x + bv[1].x; part = fmaf((x > 0.f ? x : 0.2f * x), wv[1].x, part);
        x = av[1].y + bv[1].y; part = fmaf((x > 0.f ? x : 0.2f * x), wv[1].y, part);
        x = av[1].z + bv[1].z; part = fmaf((x > 0.f ? x : 0.2f * x), wv[1].z, part);
        x = av[1].w + bv[1].w; part = fmaf((x > 0.f ? x : 0.2f * x), wv[1].w, part);
    }
    part += __shfl_xor_sync(0xffffffffu, part, 4);
    part += __shfl_xor_sync(0xffffffffu, part, 2);
    part += __shfl_xor_sync(0xffffffffu, part, 1);
    float p = __expf(part);

    float* o = out + (size_t)tn * 40;
    redv4(o + j * 4, p * av[0].x, p * av[0].y, p * av[0].z, p * av[0].w);
    if (act2)
        redv4(o + (j + 8) * 4, p * av[1].x, p * av[1].y, p * av[1].z, p * av[1].w);
    if (j == 0)
        red1(s + tn, p);
}

// ---- scale2: out = acc / (s + eps) ----
__global__ void k_scale2(float* __restrict__ out, const float* __restrict__ s) {
    int i = blockIdx.x * blockDim.x + threadIdx.x;
    if (i >= NN * 10) return;
    int t = i / 10, q = i - t * 10;
    float inv = 1.f / (__ldg(s + t) + 1e-9f);
    float4 v = *reinterpret_cast<float4*>(out + (size_t)t * 40 + q * 4);
    v.x *= inv; v.y *= inv; v.z *= inv; v.w *= inv;
    *reinterpret_cast<float4*>(out + (size_t)t * 40 + q * 4) = v;
}

// ================= launch =================
extern "C" void kernel_launch(void* const* d_in, const int* in_sizes, int n_in,
                              void* d_out, int out_size) {
    const float* x   = (const float*)d_in[0];
    const int*   src = (const int*)d_in[1];
    const int*   dst = (const int*)d_in[2];
    const float* W1s = (const float*)d_in[3];
    const float* b1s = (const float*)d_in[4];
    const float* W1d = (const float*)d_in[5];
    const float* b1d = (const float*)d_in[6];
    const float* a1  = (const float*)d_in[7];
    const float* W2s = (const float*)d_in[8];
    const float* b2s = (const float*)d_in[9];
    const float* W2d = (const float*)d_in[10];
    const float* b2d = (const float*)d_in[11];
    const float* a2  = (const float*)d_in[12];
    float* out = (float*)d_out;

    float *hs1, *hd1, *s1, *h1, *hs2, *hd2, *s2, *w1r, *w2r;
    cudaGetSymbolAddress((void**)&hs1, g_hs1);
    cudaGetSymbolAddress((void**)&hd1, g_hd1);
    cudaGetSymbolAddress((void**)&s1,  g_s1);
    cudaGetSymbolAddress((void**)&h1,  g_h1);
    cudaGetSymbolAddress((void**)&hs2, g_hs2);
    cudaGetSymbolAddress((void**)&hd2, g_hd2);
    cudaGetSymbolAddress((void**)&s2,  g_s2);
    cudaGetSymbolAddress((void**)&w1r, g_w1r);
    cudaGetSymbolAddress((void**)&w2r, g_w2r);

    const int T = 256;

    // #1-3: zeros + weight prep ; #4: gemm1 (profiled)
    k_zero2<<<(NN * FF1 + T - 1) / T, T>>>(h1, NN * FF1, s1, NN * 8);
    k_zero2<<<(NN * DD2 + T - 1) / T, T>>>(out, NN * DD2, s2, NN);
    k_round<<<(F_IN * 128 + T - 1) / T, T>>>(W1s, W1d, W2s, W2d, w1r, w2r);
    k_gemm1_mma<<<(NN + BM - 1) / BM, 256>>>(x, w1r, b1s, b1d, hs1, hd1);    // #4
    k_edge_agg1<<<EE * 16 / T, T>>>(hs1, hd1, a1, src, dst, s1, h1);

    // ---- layer 2 (normalize + ELU fused into gemm2 A staging) ----
    k_gemm2_mma<<<(NN + BM2 - 1) / BM2, 256>>>(h1, s1, w2r, b2s, b2d, hs2, hd2);
    k_edge_agg2<<<EE * 8 / T, T>>>(hs2, hd2, a2, src, dst, s2, out);
    k_scale2<<<(NN * 10 + T - 1) / T, T>>>(out, s2);
}

// round 17
// speedup vs baseline: 1.1031x; 1.0531x over previous
#include <cuda_runtime.h>
#include <math.h>

#define NN 100000
#define EE 1600000
#define F_IN 512
#define FF1 64
#define DD2 40

// ---------------- scratch ----------------
__device__ float g_hs1[NN * FF1];
__device__ float g_hd1[NN * FF1];
__device__ float g_s1[NN * 8];
__device__ float g_h1[NN * FF1];
__device__ float g_hs2[NN * DD2];
__device__ float g_hd2[NN * DD2];
__device__ float g_s2[NN];
__device__ float g_w1r[F_IN * 128];   // [k][c], c<64: W1s, else W1d (tf32-rounded)
__device__ float g_w2r[FF1 * 80];     // [k][c], c<40: W2s, else W2d (tf32-rounded)

// ---------------- PTX helpers ----------------
__device__ __forceinline__ unsigned f2tf32(float f) {
    unsigned u;
    asm("cvt.rna.tf32.f32 %0, %1;" : "=r"(u) : "f"(f));
    return u;
}
__device__ __forceinline__ void redv4(float* addr, float a, float b, float c, float d) {
    asm volatile("red.global.add.v4.f32 [%0], {%1,%2,%3,%4};"
                 :: "l"(addr), "f"(a), "f"(b), "f"(c), "f"(d) : "memory");
}
__device__ __forceinline__ void red1(float* addr, float a) {
    asm volatile("red.global.add.f32 [%0], %1;" :: "l"(addr), "f"(a) : "memory");
}
__device__ __forceinline__ void mma_tf32(float* acc, const unsigned* a, const unsigned* b) {
    asm volatile(
        "mma.sync.aligned.m16n8k8.row.col.f32.tf32.tf32.f32 "
        "{%0,%1,%2,%3}, {%4,%5,%6,%7}, {%8,%9}, {%0,%1,%2,%3};"
        : "+f"(acc[0]), "+f"(acc[1]), "+f"(acc[2]), "+f"(acc[3])
        : "r"(a[0]), "r"(a[1]), "r"(a[2]), "r"(a[3]), "r"(b[0]), "r"(b[1]));
}
__device__ __forceinline__ void cp_async16(void* smem_dst, const void* gsrc) {
    unsigned saddr = (unsigned)__cvta_generic_to_shared(smem_dst);
    asm volatile("cp.async.cg.shared.global [%0], [%1], 16;" :: "r"(saddr), "l"(gsrc));
}
__device__ __forceinline__ void cp_commit() { asm volatile("cp.async.commit_group;"); }
__device__ __forceinline__ void cp_wait0() { asm volatile("cp.async.wait_group 0;"); }

__device__ __forceinline__ float elux(float v) {
    return v > 0.f ? v : (__expf(v) - 1.f);
}

// ---------------- prep kernel ----------------
// round all weights once (RNA), write combined layouts
__global__ void k_round(const float* __restrict__ W1s, const float* __restrict__ W1d,
                        const float* __restrict__ W2s, const float* __restrict__ W2d,
                        float* __restrict__ w1r, float* __restrict__ w2r) {
    int i = blockIdx.x * blockDim.x + threadIdx.x;
    if (i < F_IN * 128) {
        int k = i >> 7, c = i & 127;
        float w = (c < 64) ? W1s[k * 64 + c] : W1d[k * 64 + (c - 64)];
        w1r[i] = __uint_as_float(f2tf32(w));
    }
    if (i < FF1 * 80) {
        int k = i / 80, c = i - k * 80;
        float w = (c < 40) ? W2s[k * 40 + c] : W2d[k * 40 + (c - 40)];
        w2r[i] = __uint_as_float(f2tf32(w));
    }
}

// ================= layer-1 GEMM: tf32 mma + fused zero of h1/s1 rows =============
#define BM 64
#define BK 16
#define APAD2 20
#define BPAD2 136
__global__ __launch_bounds__(256, 3)
void k_gemm1_mma(const float* __restrict__ A, const float* __restrict__ w1r,
                 const float* __restrict__ b1, const float* __restrict__ b2,
                 float* __restrict__ C1, float* __restrict__ C2,
                 float* __restrict__ h1z, float* __restrict__ s1z) {
    __shared__ unsigned As[2][BM * APAD2];
    __shared__ unsigned Bs[2][BK * BPAD2];

    const int tid = threadIdx.x;
    const int lane = tid & 31, warp = tid >> 5;
    const int wr = warp & 1, wc = warp >> 1;
    const int g = lane >> 2, tg = lane & 3;
    const int row0 = blockIdx.x * BM;

    // ---- fused zero-init of RED targets for rows [row0, row0+BM) ----
    {
        const float4 z4 = make_float4(0.f, 0.f, 0.f, 0.f);
#pragma unroll
        for (int i = 0; i < 4; i++) {
            int idx = tid + i * 256;                 // 1024 float4 = 64 rows x 64 f
            int r = row0 + (idx >> 4);
            if (r < NN)
                *reinterpret_cast<float4*>(h1z + (size_t)r * 64 + (idx & 15) * 4) = z4;
        }
#pragma unroll
        for (int i = 0; i < 2; i++) {
            int idx = tid + i * 256;                 // 512 floats = 64 rows x 8
            int r = row0 + (idx >> 3);
            if (r < NN) s1z[r * 8 + (idx & 7)] = 0.f;
        }
    }

    float acc[2][4][4];
#pragma unroll
    for (int mi = 0; mi < 2; mi++)
#pragma unroll
        for (int ni = 0; ni < 4; ni++)
#pragma unroll
            for (int r = 0; r < 4; r++) acc[mi][ni][r] = 0.f;

    const int rA = tid >> 2, qA = tid & 3;
    const int rAg = min(row0 + rA, NN - 1);
    const float* gA = A + (size_t)rAg * F_IN + qA * 4;
    const int sAoff = rA * APAD2 + qA * 4;

    const int kB = tid >> 5;
    const int cB = (tid & 31) * 4;
    const float* gB = w1r + kB * 128 + cB;
    const int sBoff0 = kB * BPAD2 + cB;
    const int sBoff1 = (kB + 8) * BPAD2 + cB;

    float4 aR;
    auto issueB = [&](int it, int buf) {
        const int kc = it * BK;
        cp_async16(&Bs[buf][sBoff0], gB + kc * 128);
        cp_async16(&Bs[buf][sBoff1], gB + (kc + 8) * 128);
        cp_commit();
    };
    auto loadA = [&](int it) { aR = *reinterpret_cast<const float4*>(gA + it * BK); };
    auto storeA = [&](int buf) {
        uint4 u = make_uint4(f2tf32(aR.x), f2tf32(aR.y), f2tf32(aR.z), f2tf32(aR.w));
        *reinterpret_cast<uint4*>(&As[buf][sAoff]) = u;
    };

    const int NITER = F_IN / BK;   // 32
    issueB(0, 0);
    loadA(0);
    storeA(0);
    int buf = 0;
    for (int it = 0; it < NITER; it++) {
        cp_wait0();
        __syncthreads();
        if (it + 1 < NITER) { issueB(it + 1, buf ^ 1); loadA(it + 1); }

#pragma unroll
        for (int ks = 0; ks < 2; ks++) {
            const int k0 = ks * 8;
            unsigned afr[2][4], bfr[4][2];
#pragma unroll
            for (int mi = 0; mi < 2; mi++) {
                const int base = wr * 32 + mi * 16;
                afr[mi][0] = As[buf][(base + g) * APAD2 + k0 + tg];
                afr[mi][1] = As[buf][(base + g + 8) * APAD2 + k0 + tg];
                afr[mi][2] = As[buf][(base + g) * APAD2 + k0 + tg + 4];
                afr[mi][3] = As[buf][(base + g + 8) * APAD2 + k0 + tg + 4];
            }
#pragma unroll
            for (int ni = 0; ni < 4; ni++) {
                const int col = wc * 32 + ni * 8 + g;
                bfr[ni][0] = Bs[buf][(k0 + tg) * BPAD2 + col];
                bfr[ni][1] = Bs[buf][(k0 + tg + 4) * BPAD2 + col];
            }
#pragma unroll
            for (int mi = 0; mi < 2; mi++)
#pragma unroll
                for (int ni = 0; ni < 4; ni++)
                    mma_tf32(acc[mi][ni], afr[mi], bfr[ni]);
        }
        if (it + 1 < NITER) storeA(buf ^ 1);
        buf ^= 1;
    }

    float* Cw = (wc < 2) ? C1 : C2;
    const float* bw = (wc < 2) ? b1 : b2;
    const int cbase = (wc < 2) ? wc * 32 : (wc - 2) * 32;
#pragma unroll
    for (int mi = 0; mi < 2; mi++) {
#pragma unroll
        for (int ni = 0; ni < 4; ni++) {
            const int col = cbase + ni * 8 + 2 * tg;
            const float bb0 = __ldg(bw + col), bb1 = __ldg(bw + col + 1);
            const int r0 = row0 + wr * 32 + mi * 16 + g;
            const int r1 = r0 + 8;
            if (r0 < NN) {
                float2 v = make_float2(acc[mi][ni][0] + bb0, acc[mi][ni][1] + bb1);
                *reinterpret_cast<float2*>(Cw + (size_t)r0 * 64 + col) = v;
            }
            if (r1 < NN) {
                float2 v = make_float2(acc[mi][ni][2] + bb0, acc[mi][ni][3] + bb1);
                *reinterpret_cast<float2*>(Cw + (size_t)r1 * 64 + col) = v;
            }
        }
    }
}

// ====== layer-2 GEMM: tf32 mma, fused normalize+ELU on A, fused zero out/s2 ======
#define BM2 128
#define APAD3 20
#define BPW 88
__global__ __launch_bounds__(256, 2)
void k_gemm2_mma(const float* __restrict__ Araw, const float* __restrict__ s1,
                 const float* __restrict__ w2r,
                 const float* __restrict__ b1, const float* __restrict__ b2,
                 float* __restrict__ C1, float* __restrict__ C2,
                 float* __restrict__ outz, float* __restrict__ s2z) {
    __shared__ unsigned As[2][BM2 * APAD3];
    __shared__ unsigned Bs[2][BK * BPW];

    const int tid = threadIdx.x;
    const int lane = tid & 31, warp = tid >> 5;
    const int wr = warp & 3, wc = warp >> 2;
    const int g = lane >> 2, tg = lane & 3;
    const int row0 = blockIdx.x * BM2;

    // ---- fused zero-init of RED targets for rows [row0, row0+BM2) ----
    {
        const float4 z4 = make_float4(0.f, 0.f, 0.f, 0.f);
#pragma unroll
        for (int i = 0; i < 5; i++) {
            int idx = tid + i * 256;                 // 1280 float4 = 128 rows x 40 f
            int r = row0 + idx / 10;
            if (r < NN)
                *reinterpret_cast<float4*>(outz + (size_t)r * 40 + (idx % 10) * 4) = z4;
        }
        if (tid < BM2) {
            int r = row0 + tid;
            if (r < NN) s2z[r] = 0.f;
        }
    }

    float acc[2][5][4];
#pragma unroll
    for (int mi = 0; mi < 2; mi++)
#pragma unroll
        for (int ni = 0; ni < 5; ni++)
#pragma unroll
            for (int r = 0; r < 4; r++) acc[mi][ni][r] = 0.f;

    const int rA = tid >> 2, qA = tid & 3;
    const int rAg0 = min(row0 + rA, NN - 1);
    const int rAg1 = min(row0 + rA + 64, NN - 1);
    const float* gA0 = Araw + (size_t)rAg0 * FF1 + qA * 4;
    const float* gA1 = Araw + (size_t)rAg1 * FF1 + qA * 4;
    const int sAoff0 = rA * APAD3 + qA * 4;
    const int sAoff1 = (rA + 64) * APAD3 + qA * 4;

    const int i0 = tid;
    const int kB0 = i0 / 20, c40 = i0 % 20;
    const int i1 = 256 + tid;
    const int kB1 = i1 / 20, c41 = i1 % 20;
    const int cB0 = c40 * 4, cB1 = c41 * 4;
    const float* gB0 = w2r + kB0 * 80 + cB0;
    const float* gB1 = w2r + kB1 * 80 + cB1;
    const int sB0 = kB0 * BPW + cB0;
    const int sB1 = kB1 * BPW + cB1;

    float4 aR0, aR1;
    float inv0, inv1;
    auto issueB = [&](int it, int buf) {
        const int kc = it * BK;
        cp_async16(&Bs[buf][sB0], gB0 + kc * 80);
        if (tid < 64) cp_async16(&Bs[buf][sB1], gB1 + kc * 80);
        cp_commit();
    };
    auto loadA = [&](int it) {
        aR0 = *reinterpret_cast<const float4*>(gA0 + it * BK);
        aR1 = *reinterpret_cast<const float4*>(gA1 + it * BK);
        const int head = (it * BK + qA * 4) >> 3;   // constant across the float4
        inv0 = 1.f / (__ldg(s1 + rAg0 * 8 + head) + 1e-9f);
        inv1 = 1.f / (__ldg(s1 + rAg1 * 8 + head) + 1e-9f);
    };
    auto storeA = [&](int buf) {
        uint4 u0 = make_uint4(f2tf32(elux(aR0.x * inv0)), f2tf32(elux(aR0.y * inv0)),
                              f2tf32(elux(aR0.z * inv0)), f2tf32(elux(aR0.w * inv0)));
        uint4 u1 = make_uint4(f2tf32(elux(aR1.x * inv1)), f2tf32(elux(aR1.y * inv1)),
                              f2tf32(elux(aR1.z * inv1)), f2tf32(elux(aR1.w * inv1)));
        *reinterpret_cast<uint4*>(&As[buf][sAoff0]) = u0;
        *reinterpret_cast<uint4*>(&As[buf][sAoff1]) = u1;
    };

    const int NITER = FF1 / BK;   // 4
    issueB(0, 0);
    loadA(0);
    storeA(0);
    int buf = 0;
    for (int it = 0; it < NITER; it++) {
        cp_wait0();
        __syncthreads();
        if (it + 1 < NITER) { issueB(it + 1, buf ^ 1); loadA(it + 1); }

#pragma unroll
        for (int ks = 0; ks < 2; ks++) {
            const int k0 = ks * 8;
            unsigned afr[2][4], bfr[5][2];
#pragma unroll
            for (int mi = 0; mi < 2; mi++) {
                const int base = wr * 32 + mi * 16;
                afr[mi][0] = As[buf][(base + g) * APAD3 + k0 + tg];
                afr[mi][1] = As[buf][(base + g + 8) * APAD3 + k0 + tg];
                afr[mi][2] = As[buf][(base + g) * APAD3 + k0 + tg + 4];
                afr[mi][3] = As[buf][(base + g + 8) * APAD3 + k0 + tg + 4];
            }
#pragma unroll
            for (int ni = 0; ni < 5; ni++) {
                const int col = wc * 40 + ni * 8 + g;
                bfr[ni][0] = Bs[buf][(k0 + tg) * BPW + col];
                bfr[ni][1] = Bs[buf][(k0 + tg + 4) * BPW + col];
            }
#pragma unroll
            for (int mi = 0; mi < 2; mi++)
#pragma unroll
                for (int ni = 0; ni < 5; ni++)
                    mma_tf32(acc[mi][ni], afr[mi], bfr[ni]);
        }
        if (it + 1 < NITER) storeA(buf ^ 1);
        buf ^= 1;
    }

    float* Cw = (wc == 0) ? C1 : C2;
    const float* bw = (wc == 0) ? b1 : b2;
#pragma unroll
    for (int mi = 0; mi < 2; mi++) {
#pragma unroll
        for (int ni = 0; ni < 5; ni++) {
            const int col = ni * 8 + 2 * tg;
            const float bb0 = __ldg(bw + col), bb1 = __ldg(bw + col + 1);
            const int r0 = row0 + wr * 32 + mi * 16 + g;
            const int r1 = r0 + 8;
            if (r0 < NN) {
                float2 v = make_float2(acc[mi][ni][0] + bb0, acc[mi][ni][1] + bb1);
                *reinterpret_cast<float2*>(Cw + (size_t)r0 * 40 + col) = v;
            }
            if (r1 < NN) {
                float2 v = make_float2(acc[mi][ni][2] + bb0, acc[mi][ni][3] + bb1);
                *reinterpret_cast<float2*>(Cw + (size_t)r1 * 40 + col) = v;
            }
        }
    }
}

// ========== fused layer-1 edge pass: 16 threads/edge ==========
__global__ __launch_bounds__(256)
void k_edge_agg1(const float* __restrict__ hs, const float* __restrict__ hd,
                 const float* __restrict__ attn,
                 const int* __restrict__ src, const int* __restrict__ dst,
                 float* __restrict__ s, float* __restrict__ acc) {
    int idx = blockIdx.x * blockDim.x + threadIdx.x;   // EE*16 exact
    int e = idx >> 4, j = idx & 15;
    int lane = threadIdx.x & 31;
    int sn = __ldg(src + e), tn = __ldg(dst + e);

    float4 a = *reinterpret_cast<const float4*>(hs + (size_t)sn * 64 + j * 4);
    float4 b = *reinterpret_cast<const float4*>(hd + (size_t)tn * 64 + j * 4);
    float4 w = __ldg(reinterpret_cast<const float4*>(attn + j * 4));

    float part, x;
    x = a.x + b.x; part = (x > 0.f ? x : 0.2f * x) * w.x;
    x = a.y + b.y; part = fmaf((x > 0.f ? x : 0.2f * x), w.y, part);
    x = a.z + b.z; part = fmaf((x > 0.f ? x : 0.2f * x), w.z, part);
    x = a.w + b.w; part = fmaf((x > 0.f ? x : 0.2f * x), w.w, part);
    part += __shfl_xor_sync(0xffffffffu, part, 1);
    float p = __expf(part);

    redv4(acc + (size_t)tn * 64 + j * 4, p * a.x, p * a.y, p * a.z, p * a.w);

    int base = lane & ~7;
    float v0 = __shfl_sync(0xffffffffu, p, base);
    float v1 = __shfl_sync(0xffffffffu, p, base + 2);
    float v2 = __shfl_sync(0xffffffffu, p, base + 4);
    float v3 = __shfl_sync(0xffffffffu, p, base + 6);
    if ((j & 7) == 0)
        redv4(s + (size_t)tn * 8 + (j >> 1), v0, v1, v2, v3);
}

// ========== fused layer-2 edge pass: 8 threads/edge ==========
__global__ __launch_bounds__(256)
void k_edge_agg2(const float* __restrict__ hs, const float* __restrict__ hd,
                 const float* __restrict__ attn,
                 const int* __restrict__ src, const int* __restrict__ dst,
                 float* __restrict__ s, float* __restrict__ out) {
    int idx = blockIdx.x * blockDim.x + threadIdx.x;   // EE*8 exact
    int e = idx >> 3, j = idx & 7;
    int sn = __ldg(src + e), tn = __ldg(dst + e);

    float4 av[2], bv[2], wv[2];
    bool act2 = (j < 2);
    av[0] = *reinterpret_cast<const float4*>(hs + (size_t)sn * 40 + j * 4);
    bv[0] = *reinterpret_cast<const float4*>(hd + (size_t)tn * 40 + j * 4);
    wv[0] = __ldg(reinterpret_cast<const float4*>(attn + j * 4));
    if (act2) {
        av[1] = *reinterpret_cast<const float4*>(hs + (size_t)sn * 40 + (j + 8) * 4);
        bv[1] = *reinterpret_cast<const float4*>(hd + (size_t)tn * 40 + (j + 8) * 4);
        wv[1] = __ldg(reinterpret_cast<const float4*>(attn + (j + 8) * 4));
    }

    float part = 0.f, x;
    x = av[0].x + bv[0].x; part = fmaf((x > 0.f ? x : 0.2f * x), wv[0].x, part);
    x = av[0].y + bv[0].y; part = fmaf((x > 0.f ? x : 0.2f * x), wv[0].y, part);
    x = av[0].z + bv[0].z; part = fmaf((x > 0.f ? x : 0.2f * x), wv[0].z, part);
    x = av[0].w + bv[0].w; part = fmaf((x > 0.f ? x : 0.2f * x), wv[0].w, part);
    if (act2) {
        x = av[1].x + bv[1].x; part = fmaf((x > 0.f ? x : 0.2f * x), wv[1].x, part);
        x = av[1].y + bv[1].y; part = fmaf((x > 0.f ? x : 0.2f * x), wv[1].y, part);
        x = av[1].z + bv[1].z; part = fmaf((x > 0.f ? x : 0.2f * x), wv[1].z, part);
        x = av[1].w + bv[1].w; part = fmaf((x > 0.f ? x : 0.2f * x), wv[1].w, part);
    }
    part += __shfl_xor_sync(0xffffffffu, part, 4);
    part += __shfl_xor_sync(0xffffffffu, part, 2);
    part += __shfl_xor_sync(0xffffffffu, part, 1);
    float p = __expf(part);

    float* o = out + (size_t)tn * 40;
    redv4(o + j * 4, p * av[0].x, p * av[0].y, p * av[0].z, p * av[0].w);
    if (act2)
        redv4(o + (j + 8) * 4, p * av[1].x, p * av[1].y, p * av[1].z, p * av[1].w);
    if (j == 0)
        red1(s + tn, p);
}

// ---- scale2: out = acc / (s + eps) ----
__global__ void k_scale2(float* __restrict__ out, const float* __restrict__ s) {
    int i = blockIdx.x * blockDim.x + threadIdx.x;
    if (i >= NN * 10) return;
    int t = i / 10, q = i - t * 10;
    float inv = 1.f / (__ldg(s + t) + 1e-9f);
    float4 v = *reinterpret_cast<float4*>(out + (size_t)t * 40 + q * 4);
    v.x *= inv; v.y *= inv; v.z *= inv; v.w *= inv;
    *reinterpret_cast<float4*>(out + (size_t)t * 40 + q * 4) = v;
}

// ================= launch =================
extern "C" void kernel_launch(void* const* d_in, const int* in_sizes, int n_in,
                              void* d_out, int out_size) {
    const float* x   = (const float*)d_in[0];
    const int*   src = (const int*)d_in[1];
    const int*   dst = (const int*)d_in[2];
    const float* W1s = (const float*)d_in[3];
    const float* b1s = (const float*)d_in[4];
    const float* W1d = (const float*)d_in[5];
    const float* b1d = (const float*)d_in[6];
    const float* a1  = (const float*)d_in[7];
    const float* W2s = (const float*)d_in[8];
    const float* b2s = (const float*)d_in[9];
    const float* W2d = (const float*)d_in[10];
    const float* b2d = (const float*)d_in[11];
    const float* a2  = (const float*)d_in[12];
    float* out = (float*)d_out;

    float *hs1, *hd1, *s1, *h1, *hs2, *hd2, *s2, *w1r, *w2r;
    cudaGetSymbolAddress((void**)&hs1, g_hs1);
    cudaGetSymbolAddress((void**)&hd1, g_hd1);
    cudaGetSymbolAddress((void**)&s1,  g_s1);
    cudaGetSymbolAddress((void**)&h1,  g_h1);
    cudaGetSymbolAddress((void**)&hs2, g_hs2);
    cudaGetSymbolAddress((void**)&hd2, g_hd2);
    cudaGetSymbolAddress((void**)&s2,  g_s2);
    cudaGetSymbolAddress((void**)&w1r, g_w1r);
    cudaGetSymbolAddress((void**)&w2r, g_w2r);

    const int T = 256;

    // #1: weight prep ; #2: gemm1 (+zero h1/s1) ; #3: agg1 ; #4: gemm2 (profiled)
    k_round<<<(F_IN * 128 + T - 1) / T, T>>>(W1s, W1d, W2s, W2d, w1r, w2r);
    k_gemm1_mma<<<(NN + BM - 1) / BM, 256>>>(x, w1r, b1s, b1d, hs1, hd1, h1, s1);
    k_edge_agg1<<<EE * 16 / T, T>>>(hs1, hd1, a1, src, dst, s1, h1);

    // ---- layer 2 (normalize+ELU fused into gemm2 A staging; zero out/s2 fused) --
    k_gemm2_mma<<<(NN + BM2 - 1) / BM2, 256>>>(h1, s1, w2r, b2s, b2d, hs2, hd2,
                                               out, s2);                     // #4
    k_edge_agg2<<<EE * 8 / T, T>>>(hs2, hd2, a2, src, dst, s2, out);
    k_scale2<<<(NN * 10 + T - 1) / T, T>>>(out, s2);
}